// round 1
// baseline (speedup 1.0000x reference)
#include <cuda_runtime.h>
#include <cuda_bf16.h>
#include <math.h>

// ---------------------------------------------------------------------------
// GMViT_mini pipeline, fp32 baseline (FFMA-bound).
//   K1: f_cnn  = x @ We + be                        [81920,512]  -> out
//   K2: x1     = f_cnn @ W1 + b1                    [81920,512]  -> scratch
//   K3: f_vit1 = LN(x1); att = sigmoid(f_vit1@Wa+ba)             -> out, out
//   K4: pre    = max over 20 views of x1            [4096,512]   -> scratch
//   K5: t      = pre @ W2 + b2                      [4096,512]   -> scratch
//   K6: f_vit2 = LN(t)                                           -> out
//   K7: f_global = BN(f_vit2 @ h1W + h1b); h = relu(f_global)    -> out, scratch
//   K8: h2     = relu(BN(h @ h2W + h2b))            [4096,256]   -> scratch
//   K9: pred   = h2 @ h3W + h3b                     [4096,40]    -> out
// ---------------------------------------------------------------------------

#define D512 512
#define NVIEWS 20
#define BROWS 4096
#define MROWS (BROWS * NVIEWS)   // 81920

// output offsets (flat fp32 concat of the 6-tuple)
#define OFF_FCNN    0LL
#define OFF_FVIT1   41943040LL
#define OFF_ATT     83886080LL
#define OFF_FVIT2   83968000LL
#define OFF_FGLOB   86065152LL
#define OFF_PRED    88162304LL

// scratch (device globals; no runtime allocation)
__device__ float g_x1 [(size_t)MROWS * D512];   // x1 (pre-LN mlp1 output)
__device__ float g_sa [(size_t)BROWS * D512];   // max-pooled views
__device__ float g_sb [(size_t)BROWS * D512];   // t, then h (relu'd)
__device__ float g_sc [(size_t)BROWS * 256];    // h2

// ---------------------------------------------------------------------------
// SGEMM: C[M,N] = A[M,K] @ B[K,N] + bias[N]  (+ optional per-column BN affine)
// BM=128, BN=128, BK=8, 256 threads, 8x8 microtile, double-buffered smem.
// epi: 0 = bias only
//      1 = bias, BN affine, store to C; relu -> C2
//      2 = bias, BN affine, relu, store to C
// Requires: M%128==0, N%128==0, K%8==0.
// ---------------------------------------------------------------------------
#define BM 128
#define BN 128
#define BK 8

__global__ __launch_bounds__(256, 2)
void sgemm_kernel(const float* __restrict__ A, const float* __restrict__ B,
                  const float* __restrict__ bias,
                  const float* __restrict__ gamma, const float* __restrict__ beta,
                  float* __restrict__ C, float* __restrict__ C2,
                  int M, int N, int K, int epi)
{
    __shared__ float As[2][BK][BM];
    __shared__ float Bs[2][BK][BN];

    const int tid  = threadIdx.x;
    const int row0 = blockIdx.y * BM;
    const int col0 = blockIdx.x * BN;

    // global-load mapping
    const int arow = tid >> 1;           // 0..127
    const int acol = (tid & 1) * 4;      // 0 or 4
    const int brow = tid >> 5;           // 0..7
    const int bcol = (tid & 31) * 4;     // 0..124

    // compute mapping: 16x16 thread grid, 8x8 microtile
    const int ty = tid >> 4;
    const int tx = tid & 15;

    const float* Aptr = A + (size_t)(row0 + arow) * K + acol;
    const float* Bptr = B + (size_t)brow * N + col0 + bcol;

    float acc[8][8];
#pragma unroll
    for (int i = 0; i < 8; i++)
#pragma unroll
        for (int j = 0; j < 8; j++) acc[i][j] = 0.0f;

    // prologue: tile 0 -> smem[0]
    {
        float4 a4 = *(const float4*)Aptr;
        float4 b4 = *(const float4*)Bptr;
        As[0][acol + 0][arow] = a4.x;
        As[0][acol + 1][arow] = a4.y;
        As[0][acol + 2][arow] = a4.z;
        As[0][acol + 3][arow] = a4.w;
        *(float4*)&Bs[0][brow][bcol] = b4;
    }
    __syncthreads();

    const int nk = K / BK;
    int buf = 0;

    for (int kb = 0; kb < nk; kb++) {
        float4 na, nb;
        if (kb + 1 < nk) {
            na = *(const float4*)(Aptr + (kb + 1) * BK);
            nb = *(const float4*)(Bptr + (size_t)(kb + 1) * BK * N);
        }
#pragma unroll
        for (int kk = 0; kk < BK; kk++) {
            float ar[8], br[8];
            *(float4*)&ar[0] = *(float4*)&As[buf][kk][ty * 8];
            *(float4*)&ar[4] = *(float4*)&As[buf][kk][ty * 8 + 4];
            *(float4*)&br[0] = *(float4*)&Bs[buf][kk][tx * 8];
            *(float4*)&br[4] = *(float4*)&Bs[buf][kk][tx * 8 + 4];
#pragma unroll
            for (int i = 0; i < 8; i++)
#pragma unroll
                for (int j = 0; j < 8; j++)
                    acc[i][j] = fmaf(ar[i], br[j], acc[i][j]);
        }
        if (kb + 1 < nk) {
            As[buf ^ 1][acol + 0][arow] = na.x;
            As[buf ^ 1][acol + 1][arow] = na.y;
            As[buf ^ 1][acol + 2][arow] = na.z;
            As[buf ^ 1][acol + 3][arow] = na.w;
            *(float4*)&Bs[buf ^ 1][brow][bcol] = nb;
            __syncthreads();
            buf ^= 1;
        }
    }

    // epilogue
    const float inv = rsqrtf(1.0f + 1e-5f);
    float cb[8], cg[8], cs[8];
#pragma unroll
    for (int j = 0; j < 8; j++) {
        int c = col0 + tx * 8 + j;
        cb[j] = bias[c];
        if (epi != 0) { cg[j] = gamma[c]; cs[j] = beta[c]; }
    }

#pragma unroll
    for (int i = 0; i < 8; i++) {
        int r = row0 + ty * 8 + i;
        size_t base = (size_t)r * N + col0 + tx * 8;
        float v[8];
#pragma unroll
        for (int j = 0; j < 8; j++) {
            float val = acc[i][j] + cb[j];
            if (epi != 0) val = val * inv * cg[j] + cs[j];
            v[j] = val;
        }
        if (epi == 2) {
#pragma unroll
            for (int j = 0; j < 8; j++) v[j] = fmaxf(v[j], 0.0f);
        }
        *(float4*)(C + base)     = make_float4(v[0], v[1], v[2], v[3]);
        *(float4*)(C + base + 4) = make_float4(v[4], v[5], v[6], v[7]);
        if (epi == 1) {
            *(float4*)(C2 + base)     = make_float4(fmaxf(v[0],0.f), fmaxf(v[1],0.f),
                                                    fmaxf(v[2],0.f), fmaxf(v[3],0.f));
            *(float4*)(C2 + base + 4) = make_float4(fmaxf(v[4],0.f), fmaxf(v[5],0.f),
                                                    fmaxf(v[6],0.f), fmaxf(v[7],0.f));
        }
    }
}

// ---------------------------------------------------------------------------
// LayerNorm over last dim 512 (+ optional attention score).
// One block (256 threads) per row; each thread handles 2 columns.
// att[row] = sigmoid(dot(LN(x), Wa) + ba)  when att != nullptr.
// ---------------------------------------------------------------------------
__global__ __launch_bounds__(256)
void ln_att_kernel(const float* __restrict__ X,
                   const float* __restrict__ g, const float* __restrict__ b,
                   float* __restrict__ Y,
                   const float* __restrict__ Wa, const float* __restrict__ ba,
                   float* __restrict__ att)
{
    const int row = blockIdx.x;
    const int tid = threadIdx.x;
    const float* xr = X + (size_t)row * D512;

    float x0 = xr[tid], x1 = xr[tid + 256];
    float s  = x0 + x1;
    float ss = x0 * x0 + x1 * x1;

#pragma unroll
    for (int o = 16; o > 0; o >>= 1) {
        s  += __shfl_xor_sync(0xffffffffu, s,  o);
        ss += __shfl_xor_sync(0xffffffffu, ss, o);
    }
    __shared__ float rs[8], rss[8];
    const int w = tid >> 5, lane = tid & 31;
    if (lane == 0) { rs[w] = s; rss[w] = ss; }
    __syncthreads();

    float tots = 0.f, totss = 0.f;
#pragma unroll
    for (int i = 0; i < 8; i++) { tots += rs[i]; totss += rss[i]; }

    const float mean = tots * (1.0f / 512.0f);
    const float var  = totss * (1.0f / 512.0f) - mean * mean;
    const float rstd = rsqrtf(var + 1e-5f);

    float y0 = (x0 - mean) * rstd * g[tid]       + b[tid];
    float y1 = (x1 - mean) * rstd * g[tid + 256] + b[tid + 256];

    float* yr = Y + (size_t)row * D512;
    yr[tid]       = y0;
    yr[tid + 256] = y1;

    if (att != nullptr) {
        float d = y0 * Wa[tid] + y1 * Wa[tid + 256];
#pragma unroll
        for (int o = 16; o > 0; o >>= 1)
            d += __shfl_xor_sync(0xffffffffu, d, o);
        __syncthreads();                 // protect rs[] reuse
        if (lane == 0) rs[w] = d;
        __syncthreads();
        if (tid == 0) {
            float t = 0.f;
#pragma unroll
            for (int i = 0; i < 8; i++) t += rs[i];
            att[row] = 1.0f / (1.0f + expf(-(t + ba[0])));
        }
    }
}

// ---------------------------------------------------------------------------
// Max-pool over 20 views: O[b,d] = max_v X[(b*20+v), d]
// ---------------------------------------------------------------------------
__global__ void maxpool_kernel(const float* __restrict__ X, float* __restrict__ O)
{
    int i = blockIdx.x * blockDim.x + threadIdx.x;   // 4096*512 threads
    int b = i >> 9;
    int d = i & 511;
    const float* p = X + (size_t)b * NVIEWS * D512 + d;
    float m = p[0];
#pragma unroll
    for (int v = 1; v < NVIEWS; v++) m = fmaxf(m, p[(size_t)v * D512]);
    O[i] = m;
}

// ---------------------------------------------------------------------------
// pred = h2[4096,256] @ h3W[256,40] + h3b
// ---------------------------------------------------------------------------
__global__ void pred_kernel(const float* __restrict__ H, const float* __restrict__ W,
                            const float* __restrict__ bias, float* __restrict__ P)
{
    int i = blockIdx.x * blockDim.x + threadIdx.x;   // 4096*40
    if (i >= BROWS * 40) return;
    int r = i / 40, n = i % 40;
    const float* h = H + (size_t)r * 256;
    float acc = bias[n];
#pragma unroll 8
    for (int k = 0; k < 256; k++)
        acc = fmaf(h[k], W[k * 40 + n], acc);
    P[i] = acc;
}

// ---------------------------------------------------------------------------
static float* sym_addr(const void* p) { return (float*)p; }

extern "C" void kernel_launch(void* const* d_in, const int* in_sizes, int n_in,
                              void* d_out, int out_size)
{
    const float* x     = (const float*)d_in[0];
    const float* We    = (const float*)d_in[1];
    const float* be    = (const float*)d_in[2];
    const float* W1    = (const float*)d_in[3];
    const float* b1    = (const float*)d_in[4];
    const float* Wa    = (const float*)d_in[5];
    const float* ba    = (const float*)d_in[6];
    const float* W2    = (const float*)d_in[7];
    const float* b2    = (const float*)d_in[8];
    const float* ln_g  = (const float*)d_in[9];
    const float* ln_b  = (const float*)d_in[10];
    const float* h1W   = (const float*)d_in[11];
    const float* h1b   = (const float*)d_in[12];
    const float* bn1_g = (const float*)d_in[13];
    const float* bn1_b = (const float*)d_in[14];
    const float* h2W   = (const float*)d_in[15];
    const float* h2b   = (const float*)d_in[16];
    const float* bn2_g = (const float*)d_in[17];
    const float* bn2_b = (const float*)d_in[18];
    const float* h3W   = (const float*)d_in[19];
    const float* h3b   = (const float*)d_in[20];

    float* out      = (float*)d_out;
    float* f_cnn    = out + OFF_FCNN;
    float* f_vit1   = out + OFF_FVIT1;
    float* att      = out + OFF_ATT;
    float* f_vit2   = out + OFF_FVIT2;
    float* f_global = out + OFF_FGLOB;
    float* pred     = out + OFF_PRED;

    float *x1s, *sa, *sb, *sc;
    { void* p; cudaGetSymbolAddress(&p, g_x1); x1s = (float*)p; }
    { void* p; cudaGetSymbolAddress(&p, g_sa); sa  = (float*)p; }
    { void* p; cudaGetSymbolAddress(&p, g_sb); sb  = (float*)p; }
    { void* p; cudaGetSymbolAddress(&p, g_sc); sc  = (float*)p; }

    // K1: f_cnn = x @ We + be
    sgemm_kernel<<<dim3(D512 / BN, MROWS / BM), 256>>>(
        x, We, be, nullptr, nullptr, f_cnn, nullptr, MROWS, D512, D512, 0);

    // K2: x1 = f_cnn @ W1 + b1
    sgemm_kernel<<<dim3(D512 / BN, MROWS / BM), 256>>>(
        f_cnn, W1, b1, nullptr, nullptr, x1s, nullptr, MROWS, D512, D512, 0);

    // K3: f_vit1 = LN(x1); att = sigmoid(f_vit1 @ Wa + ba)
    ln_att_kernel<<<MROWS, 256>>>(x1s, ln_g, ln_b, f_vit1, Wa, ba, att);

    // K4: max over views
    maxpool_kernel<<<(BROWS * D512) / 256, 256>>>(x1s, sa);

    // K5: t = pre @ W2 + b2
    sgemm_kernel<<<dim3(D512 / BN, BROWS / BM), 256>>>(
        sa, W2, b2, nullptr, nullptr, sb, nullptr, BROWS, D512, D512, 0);

    // K6: f_vit2 = LN(t)
    ln_att_kernel<<<BROWS, 256>>>(sb, ln_g, ln_b, f_vit2, nullptr, nullptr, nullptr);

    // K7: f_global = BN(f_vit2 @ h1W + h1b); h = relu(f_global) -> sb
    sgemm_kernel<<<dim3(D512 / BN, BROWS / BM), 256>>>(
        f_vit2, h1W, h1b, bn1_g, bn1_b, f_global, sb, BROWS, D512, D512, 1);

    // K8: h2 = relu(BN(h @ h2W + h2b)) -> sc
    sgemm_kernel<<<dim3(256 / BN, BROWS / BM), 256>>>(
        sb, h2W, h2b, bn2_g, bn2_b, sc, nullptr, BROWS, 256, D512, 2);

    // K9: pred = h2 @ h3W + h3b
    pred_kernel<<<(BROWS * 40 + 127) / 128, 128>>>(sc, h3W, h3b, pred);

    (void)in_sizes; (void)n_in; (void)out_size; (void)sym_addr;
}

// round 3
// speedup vs baseline: 2.1092x; 2.1092x over previous
#include <cuda_runtime.h>
#include <cuda_bf16.h>
#include <cstdint>
#include <math.h>

// ===========================================================================
// GMViT_mini — HMMA (mma.sync bf16) pipeline, 3-term bf16-split for fp32-class
// accuracy. All instructions are base compute_103 ISA (no sm_103a features).
// ===========================================================================

#define D512 512
#define NVIEWS 20
#define BROWS 4096
#define MROWS (BROWS * NVIEWS)   // 81920

// output offsets (flat fp32 concat of the 6-tuple)
#define OFF_FCNN    0LL
#define OFF_FVIT1   41943040LL
#define OFF_ATT     83886080LL
#define OFF_FVIT2   83968000LL
#define OFF_FGLOB   86065152LL
#define OFF_PRED    88162304LL

typedef unsigned short u16;

// -------------------- scratch (device globals, no allocs) ------------------
__device__ u16   g_xh [(size_t)MROWS * D512];
__device__ u16   g_xl [(size_t)MROWS * D512];
__device__ u16   g_fch[(size_t)MROWS * D512];
__device__ u16   g_fcl[(size_t)MROWS * D512];
__device__ float g_x1 [(size_t)MROWS * D512];
__device__ u16   g_sah[(size_t)BROWS * D512];
__device__ u16   g_sal[(size_t)BROWS * D512];
__device__ float g_sb [(size_t)BROWS * D512];
__device__ u16   g_fvh[(size_t)BROWS * D512];
__device__ u16   g_fvl[(size_t)BROWS * D512];
__device__ u16   g_hrh[(size_t)BROWS * D512];
__device__ u16   g_hrl[(size_t)BROWS * D512];
__device__ float g_sc [(size_t)BROWS * 256];
// transposed+split weights  [N, K] K-major, bf16 hi/lo
__device__ u16 g_WeTh[512 * 512], g_WeTl[512 * 512];
__device__ u16 g_W1Th[512 * 512], g_W1Tl[512 * 512];
__device__ u16 g_W2Th[512 * 512], g_W2Tl[512 * 512];
__device__ u16 g_h1Th[512 * 512], g_h1Tl[512 * 512];
__device__ u16 g_h2Th[256 * 512], g_h2Tl[256 * 512];

// ============================ helpers ======================================
__device__ __forceinline__ uint32_t smem_u32(const void* p) {
    uint32_t a;
    asm("{ .reg .u64 t; cvta.to.shared.u64 t, %1; cvt.u32.u64 %0, t; }"
        : "=r"(a) : "l"(p));
    return a;
}
#define CP16(d, s) \
    asm volatile("cp.async.cg.shared.global [%0], [%1], 16;" :: "r"(d), "l"(s))
#define CP_COMMIT() asm volatile("cp.async.commit_group;" ::)
#define CP_WAIT0()  asm volatile("cp.async.wait_group 0;" ::)

__device__ __forceinline__ void ldsm4(uint32_t& r0, uint32_t& r1, uint32_t& r2,
                                      uint32_t& r3, uint32_t addr) {
    asm volatile("ldmatrix.sync.aligned.m8n8.x4.shared.b16 {%0,%1,%2,%3}, [%4];"
                 : "=r"(r0), "=r"(r1), "=r"(r2), "=r"(r3) : "r"(addr));
}
__device__ __forceinline__ void mma16816(float* c, const uint32_t* a,
                                         const uint32_t* b) {
    asm volatile(
        "mma.sync.aligned.m16n8k16.row.col.f32.bf16.bf16.f32 "
        "{%0,%1,%2,%3}, {%4,%5,%6,%7}, {%8,%9}, {%0,%1,%2,%3};"
        : "+f"(c[0]), "+f"(c[1]), "+f"(c[2]), "+f"(c[3])
        : "r"(a[0]), "r"(a[1]), "r"(a[2]), "r"(a[3]), "r"(b[0]), "r"(b[1]));
}
__device__ __forceinline__ void split2(float a, float b, uint32_t& hi, uint32_t& lo) {
    __nv_bfloat16 ha = __float2bfloat16(a), hb = __float2bfloat16(b);
    float ra = a - __bfloat162float(ha), rb = b - __bfloat162float(hb);
    __nv_bfloat16 la = __float2bfloat16(ra), lb = __float2bfloat16(rb);
    hi = ((uint32_t)__bfloat16_as_ushort(hb) << 16) | (uint32_t)__bfloat16_as_ushort(ha);
    lo = ((uint32_t)__bfloat16_as_ushort(lb) << 16) | (uint32_t)__bfloat16_as_ushort(la);
}

// ============================ hgemm ========================================
// C[M,N] = (Ah+Al)[M,K] @ (Bh+Bl)[N,K]^T + bias    (3-term bf16 split)
// CTA 128x128, BK=32, 8 warps (64x32 each), cp.async double buffer.
// Smem tile: padded stride 40 bf16 (80 B) -> conflict-free ldmatrix.
// epi 0: C=v
//     1: C=v;            C2h/C2l = split(v)
//     2: w=bn(v); C=w;   C2h/C2l = split(relu(w))
//     3: C=relu(bn(v))
#define TILE_B   10240                    // 128 rows * 40 cols * 2B
#define STAGE_B  (4 * TILE_B)             // Ah, Al, Bh, Bl
#define SMEM_G   (2 * STAGE_B)            // 81920

__global__ __launch_bounds__(256, 2)
void hgemm(const u16* __restrict__ Ah, const u16* __restrict__ Al,
           const u16* __restrict__ Bh, const u16* __restrict__ Bl,
           const float* __restrict__ bias,
           const float* __restrict__ gamma, const float* __restrict__ beta,
           float* __restrict__ C, u16* __restrict__ C2h, u16* __restrict__ C2l,
           int M, int N, int K, int epi)
{
    extern __shared__ char sm[];
    const int tid  = threadIdx.x;
    const int lane = tid & 31;
    const int wid  = tid >> 5;
    const int wm   = wid >> 2;            // 0..1  (64-row band)
    const int wn   = wid & 3;             // 0..3  (32-col band)
    const int row0 = blockIdx.y * 128;
    const int col0 = blockIdx.x * 128;

    const u16* srcs[4] = {Ah, Al, Bh, Bl};

    float acc[4][4][4];
#pragma unroll
    for (int i = 0; i < 4; i++)
#pragma unroll
        for (int j = 0; j < 4; j++)
#pragma unroll
            for (int q = 0; q < 4; q++) acc[i][j][q] = 0.0f;

    // ---- async stage loader: 4 arrays x 128 rows x 32 cols bf16 ----
    auto load_stage = [&](int kb, int buf) {
        const int k0 = kb * 32;
        char* base = sm + buf * STAGE_B;
#pragma unroll
        for (int a = 0; a < 4; a++) {
            const int rb = (a < 2) ? row0 : col0;
            const u16* src = srcs[a];
#pragma unroll
            for (int j = 0; j < 2; j++) {
                int ch = tid + j * 256;              // 0..511
                int r = ch >> 2, c = ch & 3;
                uint32_t d = smem_u32(base + a * TILE_B + r * 80 + c * 16);
                CP16(d, src + (size_t)(rb + r) * K + k0 + c * 8);
            }
        }
    };

    load_stage(0, 0);
    CP_COMMIT();

    const int nkb = K / 32;               // 16
    for (int kb = 0; kb < nkb; kb++) {
        CP_WAIT0();
        __syncthreads();
        if (kb + 1 < nkb) { load_stage(kb + 1, (kb + 1) & 1); CP_COMMIT(); }

        char* base = sm + (kb & 1) * STAGE_B;
        const uint32_t sA = smem_u32(base);               // Ah; Al at +TILE_B
        const uint32_t sB = smem_u32(base + 2 * TILE_B);  // Bh; Bl at +TILE_B

#pragma unroll
        for (int ks = 0; ks < 2; ks++) {
            const int k0 = ks * 16;
            // ---- B fragments (both variants) ----
            uint32_t bh[8], bl[8];
#pragma unroll
            for (int nt = 0; nt < 2; nt++) {
                int n = wn * 32 + nt * 16 + ((lane >> 4) << 3) + (lane & 7);
                int k = k0 + ((lane >> 3) & 1) * 8;
                uint32_t ad = sB + (uint32_t)(n * 80 + k * 2);
                ldsm4(bh[nt*4+0], bh[nt*4+1], bh[nt*4+2], bh[nt*4+3], ad);
                ldsm4(bl[nt*4+0], bl[nt*4+1], bl[nt*4+2], bl[nt*4+3], ad + TILE_B);
            }
            // ---- A fragments + MMAs ----
#pragma unroll
            for (int mi = 0; mi < 4; mi++) {
                int m = wm * 64 + mi * 16 + (lane & 15);
                int k = k0 + (lane >> 4) * 8;
                uint32_t ad = sA + (uint32_t)(m * 80 + k * 2);
                uint32_t ah[4], al[4];
                ldsm4(ah[0], ah[1], ah[2], ah[3], ad);
                ldsm4(al[0], al[1], al[2], al[3], ad + TILE_B);
#pragma unroll
                for (int ni = 0; ni < 4; ni++) {
                    mma16816(acc[mi][ni], ah, &bh[ni * 2]);   // hi*hi
                    mma16816(acc[mi][ni], ah, &bl[ni * 2]);   // hi*lo
                    mma16816(acc[mi][ni], al, &bh[ni * 2]);   // lo*hi
                }
            }
        }
    }

    // ---- epilogue ----
    const float inv = rsqrtf(1.0f + 1e-5f);
    const int rb = row0 + wm * 64 + (lane >> 2);
    const int cb = col0 + wn * 32 + (lane & 3) * 2;

#pragma unroll
    for (int mi = 0; mi < 4; mi++) {
#pragma unroll
        for (int ni = 0; ni < 4; ni++) {
            const int c = cb + ni * 8;
            float b0 = bias[c], b1 = bias[c + 1];
            float g0 = 0.f, g1 = 0.f, s0 = 0.f, s1 = 0.f;
            if (epi >= 2) { g0 = gamma[c] * inv; g1 = gamma[c+1] * inv;
                            s0 = beta[c];       s1 = beta[c+1]; }
#pragma unroll
            for (int h = 0; h < 2; h++) {
                const int r = rb + mi * 16 + h * 8;
                float v0 = acc[mi][ni][h * 2 + 0] + b0;
                float v1 = acc[mi][ni][h * 2 + 1] + b1;
                if (epi >= 2) { v0 = v0 * g0 + s0; v1 = v1 * g1 + s1; }
                if (epi == 3) { v0 = fmaxf(v0, 0.f); v1 = fmaxf(v1, 0.f); }
                *(float2*)(C + (size_t)r * N + c) = make_float2(v0, v1);
                if (epi == 1 || epi == 2) {
                    float w0 = (epi == 2) ? fmaxf(v0, 0.f) : v0;
                    float w1 = (epi == 2) ? fmaxf(v1, 0.f) : v1;
                    uint32_t hi, lo;
                    split2(w0, w1, hi, lo);
                    *(uint32_t*)(C2h + (size_t)r * N + c) = hi;
                    *(uint32_t*)(C2l + (size_t)r * N + c) = lo;
                }
            }
        }
    }
}

// ============== weight transpose + bf16 split: W[K,N] -> T[N,K] ============
__global__ void wconv_kernel(const float* __restrict__ W, int K, int N,
                             u16* __restrict__ Th, u16* __restrict__ Tl)
{
    __shared__ float t[32][33];
    const int k0 = blockIdx.y * 32, n0 = blockIdx.x * 32;
    const int tx = threadIdx.x, ty = threadIdx.y;
    for (int i = ty; i < 32; i += 8)
        t[i][tx] = W[(size_t)(k0 + i) * N + n0 + tx];
    __syncthreads();
    for (int i = ty; i < 32; i += 8) {
        float v = t[tx][i];
        __nv_bfloat16 h = __float2bfloat16(v);
        __nv_bfloat16 l = __float2bfloat16(v - __bfloat162float(h));
        size_t o = (size_t)(n0 + i) * K + k0 + tx;
        Th[o] = __bfloat16_as_ushort(h);
        Tl[o] = __bfloat16_as_ushort(l);
    }
}

// ===================== fp32 -> bf16 hi/lo split ============================
__global__ void xsplit_kernel(const float* __restrict__ X,
                              u16* __restrict__ H, u16* __restrict__ L, int n4)
{
    int i = blockIdx.x * blockDim.x + threadIdx.x;
    if (i >= n4) return;
    float4 f = *(const float4*)(X + (size_t)i * 4);
    uint32_t h0, l0, h1, l1;
    split2(f.x, f.y, h0, l0);
    split2(f.z, f.w, h1, l1);
    *(uint2*)(H + (size_t)i * 4) = make_uint2(h0, h1);
    *(uint2*)(L + (size_t)i * 4) = make_uint2(l0, l1);
}

// ============================ LayerNorm (+att, +split) =====================
__global__ __launch_bounds__(256)
void ln_att_kernel(const float* __restrict__ X,
                   const float* __restrict__ g, const float* __restrict__ b,
                   float* __restrict__ Y,
                   const float* __restrict__ Wa, const float* __restrict__ ba,
                   float* __restrict__ att,
                   u16* __restrict__ Yh, u16* __restrict__ Yl)
{
    const int row = blockIdx.x;
    const int tid = threadIdx.x;
    const float* xr = X + (size_t)row * D512;

    float x0 = xr[tid], x1 = xr[tid + 256];
    float s = x0 + x1, ss = x0 * x0 + x1 * x1;
#pragma unroll
    for (int o = 16; o > 0; o >>= 1) {
        s  += __shfl_xor_sync(0xffffffffu, s,  o);
        ss += __shfl_xor_sync(0xffffffffu, ss, o);
    }
    __shared__ float rs[8], rss[8];
    const int w = tid >> 5, lane = tid & 31;
    if (lane == 0) { rs[w] = s; rss[w] = ss; }
    __syncthreads();
    float tots = 0.f, totss = 0.f;
#pragma unroll
    for (int i = 0; i < 8; i++) { tots += rs[i]; totss += rss[i]; }
    const float mean = tots * (1.0f / 512.0f);
    const float var  = totss * (1.0f / 512.0f) - mean * mean;
    const float rstd = rsqrtf(var + 1e-5f);
    float y0 = (x0 - mean) * rstd * g[tid]       + b[tid];
    float y1 = (x1 - mean) * rstd * g[tid + 256] + b[tid + 256];
    float* yr = Y + (size_t)row * D512;
    yr[tid] = y0; yr[tid + 256] = y1;

    if (Yh != nullptr) {
        __nv_bfloat16 h0 = __float2bfloat16(y0);
        __nv_bfloat16 h1 = __float2bfloat16(y1);
        Yh[(size_t)row * D512 + tid]       = __bfloat16_as_ushort(h0);
        Yh[(size_t)row * D512 + tid + 256] = __bfloat16_as_ushort(h1);
        Yl[(size_t)row * D512 + tid]       =
            __bfloat16_as_ushort(__float2bfloat16(y0 - __bfloat162float(h0)));
        Yl[(size_t)row * D512 + tid + 256] =
            __bfloat16_as_ushort(__float2bfloat16(y1 - __bfloat162float(h1)));
    }

    if (att != nullptr) {
        float d = y0 * Wa[tid] + y1 * Wa[tid + 256];
#pragma unroll
        for (int o = 16; o > 0; o >>= 1)
            d += __shfl_xor_sync(0xffffffffu, d, o);
        __syncthreads();
        if (lane == 0) rs[w] = d;
        __syncthreads();
        if (tid == 0) {
            float t = 0.f;
#pragma unroll
            for (int i = 0; i < 8; i++) t += rs[i];
            att[row] = 1.0f / (1.0f + expf(-(t + ba[0])));
        }
    }
}

// ============================ maxpool (split emit) =========================
__global__ void maxpool_kernel(const float* __restrict__ X,
                               u16* __restrict__ H, u16* __restrict__ L)
{
    int i = blockIdx.x * blockDim.x + threadIdx.x;   // BROWS*256
    int bb = i >> 8, d = (i & 255) * 2;
    const float* p = X + (size_t)bb * NVIEWS * D512 + d;
    float m0 = p[0], m1 = p[1];
#pragma unroll
    for (int v = 1; v < NVIEWS; v++) {
        m0 = fmaxf(m0, p[(size_t)v * D512]);
        m1 = fmaxf(m1, p[(size_t)v * D512 + 1]);
    }
    uint32_t hi, lo;
    split2(m0, m1, hi, lo);
    *(uint32_t*)(H + (size_t)bb * D512 + d) = hi;
    *(uint32_t*)(L + (size_t)bb * D512 + d) = lo;
}

// ============================ pred =========================================
__global__ void pred_kernel(const float* __restrict__ Hm, const float* __restrict__ W,
                            const float* __restrict__ bias, float* __restrict__ P)
{
    int i = blockIdx.x * blockDim.x + threadIdx.x;
    if (i >= BROWS * 40) return;
    int r = i / 40, n = i % 40;
    const float* h = Hm + (size_t)r * 256;
    float acc = bias[n];
#pragma unroll 8
    for (int k = 0; k < 256; k++)
        acc = fmaf(h[k], W[k * 40 + n], acc);
    P[i] = acc;
}

// ===========================================================================
extern "C" void kernel_launch(void* const* d_in, const int* in_sizes, int n_in,
                              void* d_out, int out_size)
{
    const float* x     = (const float*)d_in[0];
    const float* We    = (const float*)d_in[1];
    const float* be    = (const float*)d_in[2];
    const float* W1    = (const float*)d_in[3];
    const float* b1    = (const float*)d_in[4];
    const float* Wa    = (const float*)d_in[5];
    const float* ba    = (const float*)d_in[6];
    const float* W2    = (const float*)d_in[7];
    const float* b2    = (const float*)d_in[8];
    const float* ln_g  = (const float*)d_in[9];
    const float* ln_b  = (const float*)d_in[10];
    const float* h1W   = (const float*)d_in[11];
    const float* h1b   = (const float*)d_in[12];
    const float* bn1_g = (const float*)d_in[13];
    const float* bn1_b = (const float*)d_in[14];
    const float* h2W   = (const float*)d_in[15];
    const float* h2b   = (const float*)d_in[16];
    const float* bn2_g = (const float*)d_in[17];
    const float* bn2_b = (const float*)d_in[18];
    const float* h3W   = (const float*)d_in[19];
    const float* h3b   = (const float*)d_in[20];

    float* out      = (float*)d_out;
    float* f_cnn    = out + OFF_FCNN;
    float* f_vit1   = out + OFF_FVIT1;
    float* att      = out + OFF_ATT;
    float* f_vit2   = out + OFF_FVIT2;
    float* f_global = out + OFF_FGLOB;
    float* pred     = out + OFF_PRED;

    u16 *xh,*xl,*fch,*fcl,*sah,*sal,*fvh,*fvl,*hrh,*hrl;
    u16 *WeTh,*WeTl,*W1Th,*W1Tl,*W2Th,*W2Tl,*h1Th,*h1Tl,*h2Th,*h2Tl;
    float *x1s,*sb,*sc;
    { void* p; cudaGetSymbolAddress(&p, g_xh);  xh  = (u16*)p; }
    { void* p; cudaGetSymbolAddress(&p, g_xl);  xl  = (u16*)p; }
    { void* p; cudaGetSymbolAddress(&p, g_fch); fch = (u16*)p; }
    { void* p; cudaGetSymbolAddress(&p, g_fcl); fcl = (u16*)p; }
    { void* p; cudaGetSymbolAddress(&p, g_x1);  x1s = (float*)p; }
    { void* p; cudaGetSymbolAddress(&p, g_sah); sah = (u16*)p; }
    { void* p; cudaGetSymbolAddress(&p, g_sal); sal = (u16*)p; }
    { void* p; cudaGetSymbolAddress(&p, g_sb);  sb  = (float*)p; }
    { void* p; cudaGetSymbolAddress(&p, g_fvh); fvh = (u16*)p; }
    { void* p; cudaGetSymbolAddress(&p, g_fvl); fvl = (u16*)p; }
    { void* p; cudaGetSymbolAddress(&p, g_hrh); hrh = (u16*)p; }
    { void* p; cudaGetSymbolAddress(&p, g_hrl); hrl = (u16*)p; }
    { void* p; cudaGetSymbolAddress(&p, g_sc);  sc  = (float*)p; }
    { void* p; cudaGetSymbolAddress(&p, g_WeTh); WeTh = (u16*)p; }
    { void* p; cudaGetSymbolAddress(&p, g_WeTl); WeTl = (u16*)p; }
    { void* p; cudaGetSymbolAddress(&p, g_W1Th); W1Th = (u16*)p; }
    { void* p; cudaGetSymbolAddress(&p, g_W1Tl); W1Tl = (u16*)p; }
    { void* p; cudaGetSymbolAddress(&p, g_W2Th); W2Th = (u16*)p; }
    { void* p; cudaGetSymbolAddress(&p, g_W2Tl); W2Tl = (u16*)p; }
    { void* p; cudaGetSymbolAddress(&p, g_h1Th); h1Th = (u16*)p; }
    { void* p; cudaGetSymbolAddress(&p, g_h1Tl); h1Tl = (u16*)p; }
    { void* p; cudaGetSymbolAddress(&p, g_h2Th); h2Th = (u16*)p; }
    { void* p; cudaGetSymbolAddress(&p, g_h2Tl); h2Tl = (u16*)p; }

    cudaFuncSetAttribute(hgemm, cudaFuncAttributeMaxDynamicSharedMemorySize, SMEM_G);

    // weight transpose + split (tiny)
    wconv_kernel<<<dim3(16, 16), dim3(32, 8)>>>(We,  512, 512, WeTh, WeTl);
    wconv_kernel<<<dim3(16, 16), dim3(32, 8)>>>(W1,  512, 512, W1Th, W1Tl);
    wconv_kernel<<<dim3(16, 16), dim3(32, 8)>>>(W2,  512, 512, W2Th, W2Tl);
    wconv_kernel<<<dim3(16, 16), dim3(32, 8)>>>(h1W, 512, 512, h1Th, h1Tl);
    wconv_kernel<<<dim3(8,  16), dim3(32, 8)>>>(h2W, 512, 256, h2Th, h2Tl);

    // x -> bf16 hi/lo
    xsplit_kernel<<<(MROWS * D512 / 4 + 255) / 256, 256>>>(
        x, xh, xl, MROWS * D512 / 4);

    // K1: f_cnn = x @ We + be   (+ split emit for K2)
    hgemm<<<dim3(4, MROWS / 128), 256, SMEM_G>>>(
        xh, xl, WeTh, WeTl, be, nullptr, nullptr,
        f_cnn, fch, fcl, MROWS, D512, D512, 1);

    // K2: x1 = f_cnn @ W1 + b1
    hgemm<<<dim3(4, MROWS / 128), 256, SMEM_G>>>(
        fch, fcl, W1Th, W1Tl, b1, nullptr, nullptr,
        x1s, nullptr, nullptr, MROWS, D512, D512, 0);

    // K3: f_vit1 = LN(x1); att
    ln_att_kernel<<<MROWS, 256>>>(x1s, ln_g, ln_b, f_vit1, Wa, ba, att,
                                  nullptr, nullptr);

    // K4: maxpool over views (split emit)
    maxpool_kernel<<<(BROWS * 256) / 256, 256>>>(x1s, sah, sal);

    // K5: t = pre @ W2 + b2
    hgemm<<<dim3(4, BROWS / 128), 256, SMEM_G>>>(
        sah, sal, W2Th, W2Tl, b2, nullptr, nullptr,
        sb, nullptr, nullptr, BROWS, D512, D512, 0);

    // K6: f_vit2 = LN(t)  (+ split emit for K7)
    ln_att_kernel<<<BROWS, 256>>>(sb, ln_g, ln_b, f_vit2, nullptr, nullptr,
                                  nullptr, fvh, fvl);

    // K7: f_global = BN(f_vit2 @ h1W + h1b); split(relu) -> hrh/hrl
    hgemm<<<dim3(4, BROWS / 128), 256, SMEM_G>>>(
        fvh, fvl, h1Th, h1Tl, h1b, bn1_g, bn1_b,
        f_global, hrh, hrl, BROWS, D512, D512, 2);

    // K8: h2 = relu(BN(hr @ h2W + h2b))
    hgemm<<<dim3(2, BROWS / 128), 256, SMEM_G>>>(
        hrh, hrl, h2Th, h2Tl, h2b, bn2_g, bn2_b,
        sc, nullptr, nullptr, BROWS, 256, D512, 3);

    // K9: pred
    pred_kernel<<<(BROWS * 40 + 127) / 128, 128>>>(sc, h3W, h3b, pred);

    (void)in_sizes; (void)n_in; (void)out_size;
}

// round 4
// speedup vs baseline: 2.3693x; 1.1233x over previous
#include <cuda_runtime.h>
#include <cuda_bf16.h>
#include <cstdint>
#include <math.h>

// ===========================================================================
// GMViT_mini — HMMA (mma.sync bf16) pipeline, 3-term bf16-split.
// R4: xsplit fused into K1 loader; LN+att+maxpool fused; K1 at launch #6.
// ===========================================================================

#define D512 512
#define NVIEWS 20
#define BROWS 4096
#define MROWS (BROWS * NVIEWS)   // 81920

#define OFF_FCNN    0LL
#define OFF_FVIT1   41943040LL
#define OFF_ATT     83886080LL
#define OFF_FVIT2   83968000LL
#define OFF_FGLOB   86065152LL
#define OFF_PRED    88162304LL

typedef unsigned short u16;

// -------------------- scratch (device globals, no allocs) ------------------
__device__ u16   g_fch[(size_t)MROWS * D512];
__device__ u16   g_fcl[(size_t)MROWS * D512];
__device__ float g_x1 [(size_t)MROWS * D512];
__device__ u16   g_sah[(size_t)BROWS * D512];
__device__ u16   g_sal[(size_t)BROWS * D512];
__device__ float g_sb [(size_t)BROWS * D512];
__device__ u16   g_fvh[(size_t)BROWS * D512];
__device__ u16   g_fvl[(size_t)BROWS * D512];
__device__ u16   g_hrh[(size_t)BROWS * D512];
__device__ u16   g_hrl[(size_t)BROWS * D512];
__device__ float g_sc [(size_t)BROWS * 256];
__device__ u16 g_WeTh[512 * 512], g_WeTl[512 * 512];
__device__ u16 g_W1Th[512 * 512], g_W1Tl[512 * 512];
__device__ u16 g_W2Th[512 * 512], g_W2Tl[512 * 512];
__device__ u16 g_h1Th[512 * 512], g_h1Tl[512 * 512];
__device__ u16 g_h2Th[256 * 512], g_h2Tl[256 * 512];

// ============================ helpers ======================================
__device__ __forceinline__ uint32_t smem_u32(const void* p) {
    uint32_t a;
    asm("{ .reg .u64 t; cvta.to.shared.u64 t, %1; cvt.u32.u64 %0, t; }"
        : "=r"(a) : "l"(p));
    return a;
}
#define CP16(d, s) \
    asm volatile("cp.async.cg.shared.global [%0], [%1], 16;" :: "r"(d), "l"(s))
#define CP_COMMIT() asm volatile("cp.async.commit_group;" ::)
#define CP_WAIT0()  asm volatile("cp.async.wait_group 0;" ::)

__device__ __forceinline__ void ldsm4(uint32_t& r0, uint32_t& r1, uint32_t& r2,
                                      uint32_t& r3, uint32_t addr) {
    asm volatile("ldmatrix.sync.aligned.m8n8.x4.shared.b16 {%0,%1,%2,%3}, [%4];"
                 : "=r"(r0), "=r"(r1), "=r"(r2), "=r"(r3) : "r"(addr));
}
__device__ __forceinline__ void mma16816(float* c, const uint32_t* a,
                                         const uint32_t* b) {
    asm volatile(
        "mma.sync.aligned.m16n8k16.row.col.f32.bf16.bf16.f32 "
        "{%0,%1,%2,%3}, {%4,%5,%6,%7}, {%8,%9}, {%0,%1,%2,%3};"
        : "+f"(c[0]), "+f"(c[1]), "+f"(c[2]), "+f"(c[3])
        : "r"(a[0]), "r"(a[1]), "r"(a[2]), "r"(a[3]), "r"(b[0]), "r"(b[1]));
}
__device__ __forceinline__ void split2(float a, float b, uint32_t& hi, uint32_t& lo) {
    __nv_bfloat16 ha = __float2bfloat16(a), hb = __float2bfloat16(b);
    float ra = a - __bfloat162float(ha), rb = b - __bfloat162float(hb);
    __nv_bfloat16 la = __float2bfloat16(ra), lb = __float2bfloat16(rb);
    hi = ((uint32_t)__bfloat16_as_ushort(hb) << 16) | (uint32_t)__bfloat16_as_ushort(ha);
    lo = ((uint32_t)__bfloat16_as_ushort(lb) << 16) | (uint32_t)__bfloat16_as_ushort(la);
}
// monotonic float <-> uint key for atomicMax-based fmax
__device__ __forceinline__ uint32_t fkey(float f) {
    uint32_t u = __float_as_uint(f);
    return (u & 0x80000000u) ? ~u : (u | 0x80000000u);
}
__device__ __forceinline__ float funkey(uint32_t k) {
    return __uint_as_float((k & 0x80000000u) ? (k ^ 0x80000000u) : ~k);
}

// ============================ hgemm ========================================
// C[M,N] = (Ah+Al)[M,K] @ (Bh+Bl)[N,K]^T + bias   (3-term bf16 split)
// CTA 128x128, BK=32, 8 warps (64x32 each), cp.async double buffer.
// If Af != null, A is loaded fp32 and split in-kernel (reg double-buffer).
// epi 0: C=v
//     1: C=v;            C2h/C2l = split(v)
//     2: w=bn(v); C=w;   C2h/C2l = split(relu(w))
//     3: C=relu(bn(v))
#define TILE_B   10240                    // 128 rows * 40 cols * 2B
#define STAGE_B  (4 * TILE_B)             // Ah, Al, Bh, Bl
#define SMEM_G   (2 * STAGE_B)            // 81920

__global__ __launch_bounds__(256, 2)
void hgemm(const float* __restrict__ Af,
           const u16* __restrict__ Ah, const u16* __restrict__ Al,
           const u16* __restrict__ Bh, const u16* __restrict__ Bl,
           const float* __restrict__ bias,
           const float* __restrict__ gamma, const float* __restrict__ beta,
           float* __restrict__ C, u16* __restrict__ C2h, u16* __restrict__ C2l,
           int M, int N, int K, int epi)
{
    extern __shared__ char sm[];
    const int tid  = threadIdx.x;
    const int lane = tid & 31;
    const int wid  = tid >> 5;
    const int wm   = wid >> 2;
    const int wn   = wid & 3;
    const int row0 = blockIdx.y * 128;
    const int col0 = blockIdx.x * 128;
    const bool useAf = (Af != nullptr);

    float acc[4][4][4];
#pragma unroll
    for (int i = 0; i < 4; i++)
#pragma unroll
        for (int j = 0; j < 4; j++)
#pragma unroll
            for (int q = 0; q < 4; q++) acc[i][j][q] = 0.0f;

    // fp32 A-path mapping: thread t -> row t>>1, 16-col segment (t&1)*16
    const int fr = tid >> 1;
    const int fc = (tid & 1) * 16;

    // async B (and bf16-A) loader
    auto load_async = [&](int kb, int buf) {
        const int k0 = kb * 32;
        char* base = sm + buf * STAGE_B;
        if (!useAf) {
#pragma unroll
            for (int j = 0; j < 2; j++) {
                int ch = tid + j * 256;
                int r = ch >> 2, c = ch & 3;
                uint32_t d = smem_u32(base + r * 80 + c * 16);
                CP16(d, Ah + (size_t)(row0 + r) * K + k0 + c * 8);
                CP16(d + TILE_B, Al + (size_t)(row0 + r) * K + k0 + c * 8);
            }
        }
#pragma unroll
        for (int j = 0; j < 2; j++) {
            int ch = tid + j * 256;
            int r = ch >> 2, c = ch & 3;
            uint32_t d = smem_u32(base + 2 * TILE_B + r * 80 + c * 16);
            CP16(d, Bh + (size_t)(col0 + r) * K + k0 + c * 8);
            CP16(d + TILE_B, Bl + (size_t)(col0 + r) * K + k0 + c * 8);
        }
    };
    auto ldg_af = [&](int kb, float4* f) {
        const float* p = Af + (size_t)(row0 + fr) * K + kb * 32 + fc;
        f[0] = *(const float4*)p;       f[1] = *(const float4*)(p + 4);
        f[2] = *(const float4*)(p + 8); f[3] = *(const float4*)(p + 12);
    };
    auto sts_af = [&](int buf, const float4* f) {
        char* base = sm + buf * STAGE_B;
        uint4 uh0, uh1, ul0, ul1;
        split2(f[0].x, f[0].y, uh0.x, ul0.x);
        split2(f[0].z, f[0].w, uh0.y, ul0.y);
        split2(f[1].x, f[1].y, uh0.z, ul0.z);
        split2(f[1].z, f[1].w, uh0.w, ul0.w);
        split2(f[2].x, f[2].y, uh1.x, ul1.x);
        split2(f[2].z, f[2].w, uh1.y, ul1.y);
        split2(f[3].x, f[3].y, uh1.z, ul1.z);
        split2(f[3].z, f[3].w, uh1.w, ul1.w);
        char* p0 = base + fr * 80 + (fc >> 3) * 16;
        *(uint4*)(p0)              = uh0;
        *(uint4*)(p0 + 16)         = uh1;
        *(uint4*)(p0 + TILE_B)     = ul0;
        *(uint4*)(p0 + TILE_B + 16) = ul1;
    };

    // prologue
    float4 xf[4];
    if (useAf) { ldg_af(0, xf); sts_af(0, xf); }
    load_async(0, 0);
    CP_COMMIT();

    const int nkb = K / 32;
    for (int kb = 0; kb < nkb; kb++) {
        CP_WAIT0();
        __syncthreads();
        if (kb + 1 < nkb) {
            if (useAf) ldg_af(kb + 1, xf);
            load_async(kb + 1, (kb + 1) & 1);
            CP_COMMIT();
        }

        char* base = sm + (kb & 1) * STAGE_B;
        const uint32_t sA = smem_u32(base);
        const uint32_t sB = smem_u32(base + 2 * TILE_B);

#pragma unroll
        for (int ks = 0; ks < 2; ks++) {
            const int k0 = ks * 16;
            uint32_t bh[8], bl[8];
#pragma unroll
            for (int nt = 0; nt < 2; nt++) {
                int n = wn * 32 + nt * 16 + ((lane >> 4) << 3) + (lane & 7);
                int k = k0 + ((lane >> 3) & 1) * 8;
                uint32_t ad = sB + (uint32_t)(n * 80 + k * 2);
                ldsm4(bh[nt*4+0], bh[nt*4+1], bh[nt*4+2], bh[nt*4+3], ad);
                ldsm4(bl[nt*4+0], bl[nt*4+1], bl[nt*4+2], bl[nt*4+3], ad + TILE_B);
            }
#pragma unroll
            for (int mi = 0; mi < 4; mi++) {
                int m = wm * 64 + mi * 16 + (lane & 15);
                int k = k0 + (lane >> 4) * 8;
                uint32_t ad = sA + (uint32_t)(m * 80 + k * 2);
                uint32_t ah[4], al[4];
                ldsm4(ah[0], ah[1], ah[2], ah[3], ad);
                ldsm4(al[0], al[1], al[2], al[3], ad + TILE_B);
#pragma unroll
                for (int ni = 0; ni < 4; ni++) {
                    mma16816(acc[mi][ni], ah, &bh[ni * 2]);
                    mma16816(acc[mi][ni], ah, &bl[ni * 2]);
                    mma16816(acc[mi][ni], al, &bh[ni * 2]);
                }
            }
        }
        if (kb + 1 < nkb && useAf) sts_af((kb + 1) & 1, xf);
    }

    // epilogue
    const float inv = rsqrtf(1.0f + 1e-5f);
    const int rb = row0 + wm * 64 + (lane >> 2);
    const int cb = col0 + wn * 32 + (lane & 3) * 2;

#pragma unroll
    for (int mi = 0; mi < 4; mi++) {
#pragma unroll
        for (int ni = 0; ni < 4; ni++) {
            const int c = cb + ni * 8;
            float b0 = bias[c], b1 = bias[c + 1];
            float g0 = 0.f, g1 = 0.f, s0 = 0.f, s1 = 0.f;
            if (epi >= 2) { g0 = gamma[c] * inv; g1 = gamma[c+1] * inv;
                            s0 = beta[c];       s1 = beta[c+1]; }
#pragma unroll
            for (int h = 0; h < 2; h++) {
                const int r = rb + mi * 16 + h * 8;
                float v0 = acc[mi][ni][h * 2 + 0] + b0;
                float v1 = acc[mi][ni][h * 2 + 1] + b1;
                if (epi >= 2) { v0 = v0 * g0 + s0; v1 = v1 * g1 + s1; }
                if (epi == 3) { v0 = fmaxf(v0, 0.f); v1 = fmaxf(v1, 0.f); }
                *(float2*)(C + (size_t)r * N + c) = make_float2(v0, v1);
                if (epi == 1 || epi == 2) {
                    float w0 = (epi == 2) ? fmaxf(v0, 0.f) : v0;
                    float w1 = (epi == 2) ? fmaxf(v1, 0.f) : v1;
                    uint32_t hi, lo;
                    split2(w0, w1, hi, lo);
                    *(uint32_t*)(C2h + (size_t)r * N + c) = hi;
                    *(uint32_t*)(C2l + (size_t)r * N + c) = lo;
                }
            }
        }
    }
}

// ============== weight transpose + bf16 split: W[K,N] -> T[N,K] ============
__global__ void wconv_kernel(const float* __restrict__ W, int K, int N,
                             u16* __restrict__ Th, u16* __restrict__ Tl)
{
    __shared__ float t[32][33];
    const int k0 = blockIdx.y * 32, n0 = blockIdx.x * 32;
    const int tx = threadIdx.x, ty = threadIdx.y;
    for (int i = ty; i < 32; i += 8)
        t[i][tx] = W[(size_t)(k0 + i) * N + n0 + tx];
    __syncthreads();
    for (int i = ty; i < 32; i += 8) {
        float v = t[tx][i];
        __nv_bfloat16 h = __float2bfloat16(v);
        __nv_bfloat16 l = __float2bfloat16(v - __bfloat162float(h));
        size_t o = (size_t)(n0 + i) * K + k0 + tx;
        Th[o] = __bfloat16_as_ushort(h);
        Tl[o] = __bfloat16_as_ushort(l);
    }
}

// ============ fused: LN(x1)+att over 20 views, maxpool + split =============
// grid = BROWS blocks, 640 threads (20 warps, warp w -> view-row w).
__global__ __launch_bounds__(640)
void lnpool_kernel(const float* __restrict__ X,
                   const float* __restrict__ g, const float* __restrict__ b,
                   const float* __restrict__ Wa, const float* __restrict__ ba,
                   float* __restrict__ Y, float* __restrict__ att,
                   u16* __restrict__ Ph, u16* __restrict__ Pl)
{
    __shared__ uint32_t smax[512];
    const int obj  = blockIdx.x;
    const int tid  = threadIdx.x;
    const int w    = tid >> 5;      // view 0..19
    const int lane = tid & 31;

    for (int i = tid; i < 512; i += 640) smax[i] = 0u;
    __syncthreads();

    const int row = obj * NVIEWS + w;
    const float* xr = X + (size_t)row * D512;

    float xv[16];
    float s = 0.f, ss = 0.f;
#pragma unroll
    for (int i = 0; i < 16; i++) {
        float v = xr[lane + i * 32];
        xv[i] = v; s += v; ss += v * v;
    }
#pragma unroll
    for (int o = 16; o > 0; o >>= 1) {
        s  += __shfl_xor_sync(0xffffffffu, s,  o);
        ss += __shfl_xor_sync(0xffffffffu, ss, o);
    }
    const float mean = s * (1.0f / 512.0f);
    const float var  = ss * (1.0f / 512.0f) - mean * mean;
    const float rstd = rsqrtf(var + 1e-5f);

    float* yr = Y + (size_t)row * D512;
    float d = 0.f;
#pragma unroll
    for (int i = 0; i < 16; i++) {
        int c = lane + i * 32;
        float y = (xv[i] - mean) * rstd * __ldg(g + c) + __ldg(b + c);
        yr[c] = y;
        d += y * __ldg(Wa + c);
        atomicMax(&smax[c], fkey(xv[i]));
    }
#pragma unroll
    for (int o = 16; o > 0; o >>= 1)
        d += __shfl_xor_sync(0xffffffffu, d, o);
    if (lane == 0)
        att[row] = 1.0f / (1.0f + expf(-(d + ba[0])));

    __syncthreads();
    if (tid < 256) {
        int c = tid * 2;
        float m0 = funkey(smax[c]), m1 = funkey(smax[c + 1]);
        uint32_t hi, lo;
        split2(m0, m1, hi, lo);
        *(uint32_t*)(Ph + (size_t)obj * D512 + c) = hi;
        *(uint32_t*)(Pl + (size_t)obj * D512 + c) = lo;
    }
}

// ============================ LayerNorm (+split) ===========================
__global__ __launch_bounds__(256)
void ln_kernel(const float* __restrict__ X,
               const float* __restrict__ g, const float* __restrict__ b,
               float* __restrict__ Y, u16* __restrict__ Yh, u16* __restrict__ Yl)
{
    const int row = blockIdx.x;
    const int tid = threadIdx.x;
    const float* xr = X + (size_t)row * D512;

    float x0 = xr[tid], x1 = xr[tid + 256];
    float s = x0 + x1, ss = x0 * x0 + x1 * x1;
#pragma unroll
    for (int o = 16; o > 0; o >>= 1) {
        s  += __shfl_xor_sync(0xffffffffu, s,  o);
        ss += __shfl_xor_sync(0xffffffffu, ss, o);
    }
    __shared__ float rs[8], rss[8];
    const int w = tid >> 5, lane = tid & 31;
    if (lane == 0) { rs[w] = s; rss[w] = ss; }
    __syncthreads();
    float tots = 0.f, totss = 0.f;
#pragma unroll
    for (int i = 0; i < 8; i++) { tots += rs[i]; totss += rss[i]; }
    const float mean = tots * (1.0f / 512.0f);
    const float var  = totss * (1.0f / 512.0f) - mean * mean;
    const float rstd = rsqrtf(var + 1e-5f);
    float y0 = (x0 - mean) * rstd * g[tid]       + b[tid];
    float y1 = (x1 - mean) * rstd * g[tid + 256] + b[tid + 256];
    float* yr = Y + (size_t)row * D512;
    yr[tid] = y0; yr[tid + 256] = y1;

    __nv_bfloat16 h0 = __float2bfloat16(y0);
    __nv_bfloat16 h1 = __float2bfloat16(y1);
    Yh[(size_t)row * D512 + tid]       = __bfloat16_as_ushort(h0);
    Yh[(size_t)row * D512 + tid + 256] = __bfloat16_as_ushort(h1);
    Yl[(size_t)row * D512 + tid]       =
        __bfloat16_as_ushort(__float2bfloat16(y0 - __bfloat162float(h0)));
    Yl[(size_t)row * D512 + tid + 256] =
        __bfloat16_as_ushort(__float2bfloat16(y1 - __bfloat162float(h1)));
}

// ============================ pred =========================================
__global__ void pred_kernel(const float* __restrict__ Hm, const float* __restrict__ W,
                            const float* __restrict__ bias, float* __restrict__ P)
{
    int i = blockIdx.x * blockDim.x + threadIdx.x;
    if (i >= BROWS * 40) return;
    int r = i / 40, n = i % 40;
    const float* h = Hm + (size_t)r * 256;
    float acc = bias[n];
#pragma unroll 8
    for (int k = 0; k < 256; k++)
        acc = fmaf(h[k], W[k * 40 + n], acc);
    P[i] = acc;
}

// ===========================================================================
extern "C" void kernel_launch(void* const* d_in, const int* in_sizes, int n_in,
                              void* d_out, int out_size)
{
    const float* x     = (const float*)d_in[0];
    const float* We    = (const float*)d_in[1];
    const float* be    = (const float*)d_in[2];
    const float* W1    = (const float*)d_in[3];
    const float* b1    = (const float*)d_in[4];
    const float* Wa    = (const float*)d_in[5];
    const float* ba    = (const float*)d_in[6];
    const float* W2    = (const float*)d_in[7];
    const float* b2    = (const float*)d_in[8];
    const float* ln_g  = (const float*)d_in[9];
    const float* ln_b  = (const float*)d_in[10];
    const float* h1W   = (const float*)d_in[11];
    const float* h1b   = (const float*)d_in[12];
    const float* bn1_g = (const float*)d_in[13];
    const float* bn1_b = (const float*)d_in[14];
    const float* h2W   = (const float*)d_in[15];
    const float* h2b   = (const float*)d_in[16];
    const float* bn2_g = (const float*)d_in[17];
    const float* bn2_b = (const float*)d_in[18];
    const float* h3W   = (const float*)d_in[19];
    const float* h3b   = (const float*)d_in[20];

    float* out      = (float*)d_out;
    float* f_cnn    = out + OFF_FCNN;
    float* f_vit1   = out + OFF_FVIT1;
    float* att      = out + OFF_ATT;
    float* f_vit2   = out + OFF_FVIT2;
    float* f_global = out + OFF_FGLOB;
    float* pred     = out + OFF_PRED;

    u16 *fch,*fcl,*sah,*sal,*fvh,*fvl,*hrh,*hrl;
    u16 *WeTh,*WeTl,*W1Th,*W1Tl,*W2Th,*W2Tl,*h1Th,*h1Tl,*h2Th,*h2Tl;
    float *x1s,*sb,*sc;
    { void* p; cudaGetSymbolAddress(&p, g_fch); fch = (u16*)p; }
    { void* p; cudaGetSymbolAddress(&p, g_fcl); fcl = (u16*)p; }
    { void* p; cudaGetSymbolAddress(&p, g_x1);  x1s = (float*)p; }
    { void* p; cudaGetSymbolAddress(&p, g_sah); sah = (u16*)p; }
    { void* p; cudaGetSymbolAddress(&p, g_sal); sal = (u16*)p; }
    { void* p; cudaGetSymbolAddress(&p, g_sb);  sb  = (float*)p; }
    { void* p; cudaGetSymbolAddress(&p, g_fvh); fvh = (u16*)p; }
    { void* p; cudaGetSymbolAddress(&p, g_fvl); fvl = (u16*)p; }
    { void* p; cudaGetSymbolAddress(&p, g_hrh); hrh = (u16*)p; }
    { void* p; cudaGetSymbolAddress(&p, g_hrl); hrl = (u16*)p; }
    { void* p; cudaGetSymbolAddress(&p, g_sc);  sc  = (float*)p; }
    { void* p; cudaGetSymbolAddress(&p, g_WeTh); WeTh = (u16*)p; }
    { void* p; cudaGetSymbolAddress(&p, g_WeTl); WeTl = (u16*)p; }
    { void* p; cudaGetSymbolAddress(&p, g_W1Th); W1Th = (u16*)p; }
    { void* p; cudaGetSymbolAddress(&p, g_W1Tl); W1Tl = (u16*)p; }
    { void* p; cudaGetSymbolAddress(&p, g_W2Th); W2Th = (u16*)p; }
    { void* p; cudaGetSymbolAddress(&p, g_W2Tl); W2Tl = (u16*)p; }
    { void* p; cudaGetSymbolAddress(&p, g_h1Th); h1Th = (u16*)p; }
    { void* p; cudaGetSymbolAddress(&p, g_h1Tl); h1Tl = (u16*)p; }
    { void* p; cudaGetSymbolAddress(&p, g_h2Th); h2Th = (u16*)p; }
    { void* p; cudaGetSymbolAddress(&p, g_h2Tl); h2Tl = (u16*)p; }

    cudaFuncSetAttribute(hgemm, cudaFuncAttributeMaxDynamicSharedMemorySize, SMEM_G);

    // launches 1-5: weight transpose+split
    wconv_kernel<<<dim3(16, 16), dim3(32, 8)>>>(We,  512, 512, WeTh, WeTl);
    wconv_kernel<<<dim3(16, 16), dim3(32, 8)>>>(W1,  512, 512, W1Th, W1Tl);
    wconv_kernel<<<dim3(16, 16), dim3(32, 8)>>>(W2,  512, 512, W2Th, W2Tl);
    wconv_kernel<<<dim3(16, 16), dim3(32, 8)>>>(h1W, 512, 512, h1Th, h1Tl);
    wconv_kernel<<<dim3(8,  16), dim3(32, 8)>>>(h2W, 512, 256, h2Th, h2Tl);

    // launch 6 (ncu -s 5 target): K1 f_cnn = x @ We + be  (fp32 A, split emit)
    hgemm<<<dim3(4, MROWS / 128), 256, SMEM_G>>>(
        x, nullptr, nullptr, WeTh, WeTl, be, nullptr, nullptr,
        f_cnn, fch, fcl, MROWS, D512, D512, 1);

    // K2: x1 = f_cnn @ W1 + b1
    hgemm<<<dim3(4, MROWS / 128), 256, SMEM_G>>>(
        nullptr, fch, fcl, W1Th, W1Tl, b1, nullptr, nullptr,
        x1s, nullptr, nullptr, MROWS, D512, D512, 0);

    // K3+K4 fused: f_vit1 = LN(x1); att; maxpool(x1) -> sah/sal
    lnpool_kernel<<<BROWS, 640>>>(x1s, ln_g, ln_b, Wa, ba,
                                  f_vit1, att, sah, sal);

    // K5: t = pre @ W2 + b2
    hgemm<<<dim3(4, BROWS / 128), 256, SMEM_G>>>(
        nullptr, sah, sal, W2Th, W2Tl, b2, nullptr, nullptr,
        sb, nullptr, nullptr, BROWS, D512, D512, 0);

    // K6: f_vit2 = LN(t) (+ split emit)
    ln_kernel<<<BROWS, 256>>>(sb, ln_g, ln_b, f_vit2, fvh, fvl);

    // K7: f_global = BN(f_vit2 @ h1W + h1b); split(relu) -> hrh/hrl
    hgemm<<<dim3(4, BROWS / 128), 256, SMEM_G>>>(
        nullptr, fvh, fvl, h1Th, h1Tl, h1b, bn1_g, bn1_b,
        f_global, hrh, hrl, BROWS, D512, D512, 2);

    // K8: h2 = relu(BN(hr @ h2W + h2b))
    hgemm<<<dim3(2, BROWS / 128), 256, SMEM_G>>>(
        nullptr, hrh, hrl, h2Th, h2Tl, h2b, bn2_g, bn2_b,
        sc, nullptr, nullptr, BROWS, 256, D512, 3);

    // K9: pred
    pred_kernel<<<(BROWS * 40 + 127) / 128, 128>>>(sc, h3W, h3b, pred);

    (void)in_sizes; (void)n_in; (void)out_size;
}

// round 5
// speedup vs baseline: 2.4002x; 1.0130x over previous
#include <cuda_runtime.h>
#include <cuda_bf16.h>
#include <cstdint>
#include <math.h>

// ===========================================================================
// GMViT_mini — HMMA (mma.sync bf16) pipeline, 3-term bf16-split.
// R5: batched wconv (1 launch), reorder so profiled launch ~ K1/K2 hgemm.
// ===========================================================================

#define D512 512
#define NVIEWS 20
#define BROWS 4096
#define MROWS (BROWS * NVIEWS)   // 81920

#define OFF_FCNN    0LL
#define OFF_FVIT1   41943040LL
#define OFF_ATT     83886080LL
#define OFF_FVIT2   83968000LL
#define OFF_FGLOB   86065152LL
#define OFF_PRED    88162304LL

typedef unsigned short u16;

// -------------------- scratch (device globals, no allocs) ------------------
__device__ u16   g_fch[(size_t)MROWS * D512];
__device__ u16   g_fcl[(size_t)MROWS * D512];
__device__ float g_x1 [(size_t)MROWS * D512];
__device__ u16   g_sah[(size_t)BROWS * D512];
__device__ u16   g_sal[(size_t)BROWS * D512];
__device__ float g_sb [(size_t)BROWS * D512];
__device__ u16   g_fvh[(size_t)BROWS * D512];
__device__ u16   g_fvl[(size_t)BROWS * D512];
__device__ u16   g_hrh[(size_t)BROWS * D512];
__device__ u16   g_hrl[(size_t)BROWS * D512];
__device__ float g_sc [(size_t)BROWS * 256];
__device__ u16 g_WeTh[512 * 512], g_WeTl[512 * 512];
__device__ u16 g_W1Th[512 * 512], g_W1Tl[512 * 512];
__device__ u16 g_W2Th[512 * 512], g_W2Tl[512 * 512];
__device__ u16 g_h1Th[512 * 512], g_h1Tl[512 * 512];
__device__ u16 g_h2Th[256 * 512], g_h2Tl[256 * 512];

// ============================ helpers ======================================
__device__ __forceinline__ uint32_t smem_u32(const void* p) {
    uint32_t a;
    asm("{ .reg .u64 t; cvta.to.shared.u64 t, %1; cvt.u32.u64 %0, t; }"
        : "=r"(a) : "l"(p));
    return a;
}
#define CP16(d, s) \
    asm volatile("cp.async.cg.shared.global [%0], [%1], 16;" :: "r"(d), "l"(s))
#define CP_COMMIT() asm volatile("cp.async.commit_group;" ::)
#define CP_WAIT0()  asm volatile("cp.async.wait_group 0;" ::)

__device__ __forceinline__ void ldsm4(uint32_t& r0, uint32_t& r1, uint32_t& r2,
                                      uint32_t& r3, uint32_t addr) {
    asm volatile("ldmatrix.sync.aligned.m8n8.x4.shared.b16 {%0,%1,%2,%3}, [%4];"
                 : "=r"(r0), "=r"(r1), "=r"(r2), "=r"(r3) : "r"(addr));
}
__device__ __forceinline__ void mma16816(float* c, const uint32_t* a,
                                         const uint32_t* b) {
    asm volatile(
        "mma.sync.aligned.m16n8k16.row.col.f32.bf16.bf16.f32 "
        "{%0,%1,%2,%3}, {%4,%5,%6,%7}, {%8,%9}, {%0,%1,%2,%3};"
        : "+f"(c[0]), "+f"(c[1]), "+f"(c[2]), "+f"(c[3])
        : "r"(a[0]), "r"(a[1]), "r"(a[2]), "r"(a[3]), "r"(b[0]), "r"(b[1]));
}
__device__ __forceinline__ void split2(float a, float b, uint32_t& hi, uint32_t& lo) {
    __nv_bfloat16 ha = __float2bfloat16(a), hb = __float2bfloat16(b);
    float ra = a - __bfloat162float(ha), rb = b - __bfloat162float(hb);
    __nv_bfloat16 la = __float2bfloat16(ra), lb = __float2bfloat16(rb);
    hi = ((uint32_t)__bfloat16_as_ushort(hb) << 16) | (uint32_t)__bfloat16_as_ushort(ha);
    lo = ((uint32_t)__bfloat16_as_ushort(lb) << 16) | (uint32_t)__bfloat16_as_ushort(la);
}
__device__ __forceinline__ uint32_t fkey(float f) {
    uint32_t u = __float_as_uint(f);
    return (u & 0x80000000u) ? ~u : (u | 0x80000000u);
}
__device__ __forceinline__ float funkey(uint32_t k) {
    return __uint_as_float((k & 0x80000000u) ? (k ^ 0x80000000u) : ~k);
}

// ============================ hgemm ========================================
// C[M,N] = (Ah+Al)[M,K] @ (Bh+Bl)[N,K]^T + bias   (3-term bf16 split)
// CTA 128x128, BK=32, 8 warps (64x32 each), cp.async double buffer.
// If Af != null, A is loaded fp32 and split in-kernel.
// epi 0: C=v
//     1: C=v;            C2h/C2l = split(v)
//     2: w=bn(v); C=w;   C2h/C2l = split(relu(w))
//     3: C=relu(bn(v))
#define TILE_B   10240
#define STAGE_B  (4 * TILE_B)
#define SMEM_G   (2 * STAGE_B)

__global__ __launch_bounds__(256, 2)
void hgemm(const float* __restrict__ Af,
           const u16* __restrict__ Ah, const u16* __restrict__ Al,
           const u16* __restrict__ Bh, const u16* __restrict__ Bl,
           const float* __restrict__ bias,
           const float* __restrict__ gamma, const float* __restrict__ beta,
           float* __restrict__ C, u16* __restrict__ C2h, u16* __restrict__ C2l,
           int M, int N, int K, int epi)
{
    extern __shared__ char sm[];
    const int tid  = threadIdx.x;
    const int lane = tid & 31;
    const int wid  = tid >> 5;
    const int wm   = wid >> 2;
    const int wn   = wid & 3;
    const int row0 = blockIdx.y * 128;
    const int col0 = blockIdx.x * 128;
    const bool useAf = (Af != nullptr);

    float acc[4][4][4];
#pragma unroll
    for (int i = 0; i < 4; i++)
#pragma unroll
        for (int j = 0; j < 4; j++)
#pragma unroll
            for (int q = 0; q < 4; q++) acc[i][j][q] = 0.0f;

    const int fr = tid >> 1;
    const int fc = (tid & 1) * 16;

    auto load_async = [&](int kb, int buf) {
        const int k0 = kb * 32;
        char* base = sm + buf * STAGE_B;
        if (!useAf) {
#pragma unroll
            for (int j = 0; j < 2; j++) {
                int ch = tid + j * 256;
                int r = ch >> 2, c = ch & 3;
                uint32_t d = smem_u32(base + r * 80 + c * 16);
                CP16(d, Ah + (size_t)(row0 + r) * K + k0 + c * 8);
                CP16(d + TILE_B, Al + (size_t)(row0 + r) * K + k0 + c * 8);
            }
        }
#pragma unroll
        for (int j = 0; j < 2; j++) {
            int ch = tid + j * 256;
            int r = ch >> 2, c = ch & 3;
            uint32_t d = smem_u32(base + 2 * TILE_B + r * 80 + c * 16);
            CP16(d, Bh + (size_t)(col0 + r) * K + k0 + c * 8);
            CP16(d + TILE_B, Bl + (size_t)(col0 + r) * K + k0 + c * 8);
        }
    };
    auto ldg_af = [&](int kb, float4* f) {
        const float* p = Af + (size_t)(row0 + fr) * K + kb * 32 + fc;
        f[0] = *(const float4*)p;       f[1] = *(const float4*)(p + 4);
        f[2] = *(const float4*)(p + 8); f[3] = *(const float4*)(p + 12);
    };
    auto sts_af = [&](int buf, const float4* f) {
        char* base = sm + buf * STAGE_B;
        uint4 uh0, uh1, ul0, ul1;
        split2(f[0].x, f[0].y, uh0.x, ul0.x);
        split2(f[0].z, f[0].w, uh0.y, ul0.y);
        split2(f[1].x, f[1].y, uh0.z, ul0.z);
        split2(f[1].z, f[1].w, uh0.w, ul0.w);
        split2(f[2].x, f[2].y, uh1.x, ul1.x);
        split2(f[2].z, f[2].w, uh1.y, ul1.y);
        split2(f[3].x, f[3].y, uh1.z, ul1.z);
        split2(f[3].z, f[3].w, uh1.w, ul1.w);
        char* p0 = base + fr * 80 + (fc >> 3) * 16;
        *(uint4*)(p0)               = uh0;
        *(uint4*)(p0 + 16)          = uh1;
        *(uint4*)(p0 + TILE_B)      = ul0;
        *(uint4*)(p0 + TILE_B + 16) = ul1;
    };

    float4 xf[4];
    if (useAf) { ldg_af(0, xf); sts_af(0, xf); }
    load_async(0, 0);
    CP_COMMIT();

    const int nkb = K / 32;
    for (int kb = 0; kb < nkb; kb++) {
        CP_WAIT0();
        __syncthreads();
        if (kb + 1 < nkb) {
            if (useAf) ldg_af(kb + 1, xf);
            load_async(kb + 1, (kb + 1) & 1);
            CP_COMMIT();
        }

        char* base = sm + (kb & 1) * STAGE_B;
        const uint32_t sA = smem_u32(base);
        const uint32_t sB = smem_u32(base + 2 * TILE_B);

#pragma unroll
        for (int ks = 0; ks < 2; ks++) {
            const int k0 = ks * 16;
            uint32_t bh[8], bl[8];
#pragma unroll
            for (int nt = 0; nt < 2; nt++) {
                int n = wn * 32 + nt * 16 + ((lane >> 4) << 3) + (lane & 7);
                int k = k0 + ((lane >> 3) & 1) * 8;
                uint32_t ad = sB + (uint32_t)(n * 80 + k * 2);
                ldsm4(bh[nt*4+0], bh[nt*4+1], bh[nt*4+2], bh[nt*4+3], ad);
                ldsm4(bl[nt*4+0], bl[nt*4+1], bl[nt*4+2], bl[nt*4+3], ad + TILE_B);
            }
#pragma unroll
            for (int mi = 0; mi < 4; mi++) {
                int m = wm * 64 + mi * 16 + (lane & 15);
                int k = k0 + (lane >> 4) * 8;
                uint32_t ad = sA + (uint32_t)(m * 80 + k * 2);
                uint32_t ah[4], al[4];
                ldsm4(ah[0], ah[1], ah[2], ah[3], ad);
                ldsm4(al[0], al[1], al[2], al[3], ad + TILE_B);
#pragma unroll
                for (int ni = 0; ni < 4; ni++) {
                    mma16816(acc[mi][ni], ah, &bh[ni * 2]);
                    mma16816(acc[mi][ni], ah, &bl[ni * 2]);
                    mma16816(acc[mi][ni], al, &bh[ni * 2]);
                }
            }
        }
        if (kb + 1 < nkb && useAf) sts_af((kb + 1) & 1, xf);
    }

    // epilogue
    const float inv = rsqrtf(1.0f + 1e-5f);
    const int rb = row0 + wm * 64 + (lane >> 2);
    const int cb = col0 + wn * 32 + (lane & 3) * 2;

#pragma unroll
    for (int mi = 0; mi < 4; mi++) {
#pragma unroll
        for (int ni = 0; ni < 4; ni++) {
            const int c = cb + ni * 8;
            float b0 = bias[c], b1 = bias[c + 1];
            float g0 = 0.f, g1 = 0.f, s0 = 0.f, s1 = 0.f;
            if (epi >= 2) { g0 = gamma[c] * inv; g1 = gamma[c+1] * inv;
                            s0 = beta[c];       s1 = beta[c+1]; }
#pragma unroll
            for (int h = 0; h < 2; h++) {
                const int r = rb + mi * 16 + h * 8;
                float v0 = acc[mi][ni][h * 2 + 0] + b0;
                float v1 = acc[mi][ni][h * 2 + 1] + b1;
                if (epi >= 2) { v0 = v0 * g0 + s0; v1 = v1 * g1 + s1; }
                if (epi == 3) { v0 = fmaxf(v0, 0.f); v1 = fmaxf(v1, 0.f); }
                *(float2*)(C + (size_t)r * N + c) = make_float2(v0, v1);
                if (epi == 1 || epi == 2) {
                    float w0 = (epi == 2) ? fmaxf(v0, 0.f) : v0;
                    float w1 = (epi == 2) ? fmaxf(v1, 0.f) : v1;
                    uint32_t hi, lo;
                    split2(w0, w1, hi, lo);
                    *(uint32_t*)(C2h + (size_t)r * N + c) = hi;
                    *(uint32_t*)(C2l + (size_t)r * N + c) = lo;
                }
            }
        }
    }
}

// ======= batched weight transpose + bf16 split: W[K,N] -> T[N,K] ===========
// gridDim = (16, 16, 5); z selects matrix. z==4 (h2W, N=256) masks x>=8.
__global__ __launch_bounds__(256)
void wconv_all(const float* __restrict__ We,  u16* WeTh, u16* WeTl,
               const float* __restrict__ W1,  u16* W1Th, u16* W1Tl,
               const float* __restrict__ W2,  u16* W2Th, u16* W2Tl,
               const float* __restrict__ h1W, u16* h1Th, u16* h1Tl,
               const float* __restrict__ h2W, u16* h2Th, u16* h2Tl)
{
    const int z = blockIdx.z;
    const float* W; u16* Th; u16* Tl; int N;
    switch (z) {
        case 0: W = We;  Th = WeTh; Tl = WeTl; N = 512; break;
        case 1: W = W1;  Th = W1Th; Tl = W1Tl; N = 512; break;
        case 2: W = W2;  Th = W2Th; Tl = W2Tl; N = 512; break;
        case 3: W = h1W; Th = h1Th; Tl = h1Tl; N = 512; break;
        default:W = h2W; Th = h2Th; Tl = h2Tl; N = 256; break;
    }
    const int n0 = blockIdx.x * 32;
    if (n0 >= N) return;
    const int k0 = blockIdx.y * 32;
    const int K = 512;

    __shared__ float t[32][33];
    const int tx = threadIdx.x & 31, ty = threadIdx.x >> 5;   // 32 x 8
#pragma unroll
    for (int i = ty; i < 32; i += 8)
        t[i][tx] = W[(size_t)(k0 + i) * N + n0 + tx];
    __syncthreads();
#pragma unroll
    for (int i = ty; i < 32; i += 8) {
        float v = t[tx][i];
        __nv_bfloat16 h = __float2bfloat16(v);
        __nv_bfloat16 l = __float2bfloat16(v - __bfloat162float(h));
        size_t o = (size_t)(n0 + i) * K + k0 + tx;
        Th[o] = __bfloat16_as_ushort(h);
        Tl[o] = __bfloat16_as_ushort(l);
    }
}

// ============ fused: LN(x1)+att over 20 views, maxpool + split =============
__global__ __launch_bounds__(640)
void lnpool_kernel(const float* __restrict__ X,
                   const float* __restrict__ g, const float* __restrict__ b,
                   const float* __restrict__ Wa, const float* __restrict__ ba,
                   float* __restrict__ Y, float* __restrict__ att,
                   u16* __restrict__ Ph, u16* __restrict__ Pl)
{
    __shared__ uint32_t smax[512];
    const int obj  = blockIdx.x;
    const int tid  = threadIdx.x;
    const int w    = tid >> 5;
    const int lane = tid & 31;

    for (int i = tid; i < 512; i += 640) smax[i] = 0u;
    __syncthreads();

    const int row = obj * NVIEWS + w;
    const float* xr = X + (size_t)row * D512;

    float xv[16];
    float s = 0.f, ss = 0.f;
#pragma unroll
    for (int i = 0; i < 16; i++) {
        float v = xr[lane + i * 32];
        xv[i] = v; s += v; ss += v * v;
    }
#pragma unroll
    for (int o = 16; o > 0; o >>= 1) {
        s  += __shfl_xor_sync(0xffffffffu, s,  o);
        ss += __shfl_xor_sync(0xffffffffu, ss, o);
    }
    const float mean = s * (1.0f / 512.0f);
    const float var  = ss * (1.0f / 512.0f) - mean * mean;
    const float rstd = rsqrtf(var + 1e-5f);

    float* yr = Y + (size_t)row * D512;
    float d = 0.f;
#pragma unroll
    for (int i = 0; i < 16; i++) {
        int c = lane + i * 32;
        float y = (xv[i] - mean) * rstd * __ldg(g + c) + __ldg(b + c);
        yr[c] = y;
        d += y * __ldg(Wa + c);
        atomicMax(&smax[c], fkey(xv[i]));
    }
#pragma unroll
    for (int o = 16; o > 0; o >>= 1)
        d += __shfl_xor_sync(0xffffffffu, d, o);
    if (lane == 0)
        att[row] = 1.0f / (1.0f + expf(-(d + ba[0])));

    __syncthreads();
    if (tid < 256) {
        int c = tid * 2;
        float m0 = funkey(smax[c]), m1 = funkey(smax[c + 1]);
        uint32_t hi, lo;
        split2(m0, m1, hi, lo);
        *(uint32_t*)(Ph + (size_t)obj * D512 + c) = hi;
        *(uint32_t*)(Pl + (size_t)obj * D512 + c) = lo;
    }
}

// ============================ LayerNorm (+split) ===========================
__global__ __launch_bounds__(256)
void ln_kernel(const float* __restrict__ X,
               const float* __restrict__ g, const float* __restrict__ b,
               float* __restrict__ Y, u16* __restrict__ Yh, u16* __restrict__ Yl)
{
    const int row = blockIdx.x;
    const int tid = threadIdx.x;
    const float* xr = X + (size_t)row * D512;

    float x0 = xr[tid], x1 = xr[tid + 256];
    float s = x0 + x1, ss = x0 * x0 + x1 * x1;
#pragma unroll
    for (int o = 16; o > 0; o >>= 1) {
        s  += __shfl_xor_sync(0xffffffffu, s,  o);
        ss += __shfl_xor_sync(0xffffffffu, ss, o);
    }
    __shared__ float rs[8], rss[8];
    const int w = tid >> 5, lane = tid & 31;
    if (lane == 0) { rs[w] = s; rss[w] = ss; }
    __syncthreads();
    float tots = 0.f, totss = 0.f;
#pragma unroll
    for (int i = 0; i < 8; i++) { tots += rs[i]; totss += rss[i]; }
    const float mean = tots * (1.0f / 512.0f);
    const float var  = totss * (1.0f / 512.0f) - mean * mean;
    const float rstd = rsqrtf(var + 1e-5f);
    float y0 = (x0 - mean) * rstd * g[tid]       + b[tid];
    float y1 = (x1 - mean) * rstd * g[tid + 256] + b[tid + 256];
    float* yr = Y + (size_t)row * D512;
    yr[tid] = y0; yr[tid + 256] = y1;

    __nv_bfloat16 h0 = __float2bfloat16(y0);
    __nv_bfloat16 h1 = __float2bfloat16(y1);
    Yh[(size_t)row * D512 + tid]       = __bfloat16_as_ushort(h0);
    Yh[(size_t)row * D512 + tid + 256] = __bfloat16_as_ushort(h1);
    Yl[(size_t)row * D512 + tid]       =
        __bfloat16_as_ushort(__float2bfloat16(y0 - __bfloat162float(h0)));
    Yl[(size_t)row * D512 + tid + 256] =
        __bfloat16_as_ushort(__float2bfloat16(y1 - __bfloat162float(h1)));
}

// ============================ pred =========================================
__global__ void pred_kernel(const float* __restrict__ Hm, const float* __restrict__ W,
                            const float* __restrict__ bias, float* __restrict__ P)
{
    int i = blockIdx.x * blockDim.x + threadIdx.x;
    if (i >= BROWS * 40) return;
    int r = i / 40, n = i % 40;
    const float* h = Hm + (size_t)r * 256;
    float acc = bias[n];
#pragma unroll 8
    for (int k = 0; k < 256; k++)
        acc = fmaf(h[k], W[k * 40 + n], acc);
    P[i] = acc;
}

// ===========================================================================
extern "C" void kernel_launch(void* const* d_in, const int* in_sizes, int n_in,
                              void* d_out, int out_size)
{
    const float* x     = (const float*)d_in[0];
    const float* We    = (const float*)d_in[1];
    const float* be    = (const float*)d_in[2];
    const float* W1    = (const float*)d_in[3];
    const float* b1    = (const float*)d_in[4];
    const float* Wa    = (const float*)d_in[5];
    const float* ba    = (const float*)d_in[6];
    const float* W2    = (const float*)d_in[7];
    const float* b2    = (const float*)d_in[8];
    const float* ln_g  = (const float*)d_in[9];
    const float* ln_b  = (const float*)d_in[10];
    const float* h1W   = (const float*)d_in[11];
    const float* h1b   = (const float*)d_in[12];
    const float* bn1_g = (const float*)d_in[13];
    const float* bn1_b = (const float*)d_in[14];
    const float* h2W   = (const float*)d_in[15];
    const float* h2b   = (const float*)d_in[16];
    const float* bn2_g = (const float*)d_in[17];
    const float* bn2_b = (const float*)d_in[18];
    const float* h3W   = (const float*)d_in[19];
    const float* h3b   = (const float*)d_in[20];

    float* out      = (float*)d_out;
    float* f_cnn    = out + OFF_FCNN;
    float* f_vit1   = out + OFF_FVIT1;
    float* att      = out + OFF_ATT;
    float* f_vit2   = out + OFF_FVIT2;
    float* f_global = out + OFF_FGLOB;
    float* pred     = out + OFF_PRED;

    u16 *fch,*fcl,*sah,*sal,*fvh,*fvl,*hrh,*hrl;
    u16 *WeTh,*WeTl,*W1Th,*W1Tl,*W2Th,*W2Tl,*h1Th,*h1Tl,*h2Th,*h2Tl;
    float *x1s,*sb,*sc;
    { void* p; cudaGetSymbolAddress(&p, g_fch); fch = (u16*)p; }
    { void* p; cudaGetSymbolAddress(&p, g_fcl); fcl = (u16*)p; }
    { void* p; cudaGetSymbolAddress(&p, g_x1);  x1s = (float*)p; }
    { void* p; cudaGetSymbolAddress(&p, g_sah); sah = (u16*)p; }
    { void* p; cudaGetSymbolAddress(&p, g_sal); sal = (u16*)p; }
    { void* p; cudaGetSymbolAddress(&p, g_sb);  sb  = (float*)p; }
    { void* p; cudaGetSymbolAddress(&p, g_fvh); fvh = (u16*)p; }
    { void* p; cudaGetSymbolAddress(&p, g_fvl); fvl = (u16*)p; }
    { void* p; cudaGetSymbolAddress(&p, g_hrh); hrh = (u16*)p; }
    { void* p; cudaGetSymbolAddress(&p, g_hrl); hrl = (u16*)p; }
    { void* p; cudaGetSymbolAddress(&p, g_sc);  sc  = (float*)p; }
    { void* p; cudaGetSymbolAddress(&p, g_WeTh); WeTh = (u16*)p; }
    { void* p; cudaGetSymbolAddress(&p, g_WeTl); WeTl = (u16*)p; }
    { void* p; cudaGetSymbolAddress(&p, g_W1Th); W1Th = (u16*)p; }
    { void* p; cudaGetSymbolAddress(&p, g_W1Tl); W1Tl = (u16*)p; }
    { void* p; cudaGetSymbolAddress(&p, g_W2Th); W2Th = (u16*)p; }
    { void* p; cudaGetSymbolAddress(&p, g_W2Tl); W2Tl = (u16*)p; }
    { void* p; cudaGetSymbolAddress(&p, g_h1Th); h1Th = (u16*)p; }
    { void* p; cudaGetSymbolAddress(&p, g_h1Tl); h1Tl = (u16*)p; }
    { void* p; cudaGetSymbolAddress(&p, g_h2Th); h2Th = (u16*)p; }
    { void* p; cudaGetSymbolAddress(&p, g_h2Tl); h2Tl = (u16*)p; }

    cudaFuncSetAttribute(hgemm, cudaFuncAttributeMaxDynamicSharedMemorySize, SMEM_G);

    // launch 1: all weight transposes+splits in one grid
    wconv_all<<<dim3(16, 16, 5), 256>>>(We, WeTh, WeTl, W1, W1Th, W1Tl,
                                        W2, W2Th, W2Tl, h1W, h1Th, h1Tl,
                                        h2W, h2Th, h2Tl);

    // launch 2: K1 f_cnn = x @ We + be  (fp32 A, split emit)
    hgemm<<<dim3(4, MROWS / 128), 256, SMEM_G>>>(
        x, nullptr, nullptr, WeTh, WeTl, be, nullptr, nullptr,
        f_cnn, fch, fcl, MROWS, D512, D512, 1);

    // launch 3: K2 x1 = f_cnn @ W1 + b1
    hgemm<<<dim3(4, MROWS / 128), 256, SMEM_G>>>(
        nullptr, fch, fcl, W1Th, W1Tl, b1, nullptr, nullptr,
        x1s, nullptr, nullptr, MROWS, D512, D512, 0);

    // launch 4: fused LN + att + maxpool + split
    lnpool_kernel<<<BROWS, 640>>>(x1s, ln_g, ln_b, Wa, ba,
                                  f_vit1, att, sah, sal);

    // launch 5: K5 t = pre @ W2 + b2
    hgemm<<<dim3(4, BROWS / 128), 256, SMEM_G>>>(
        nullptr, sah, sal, W2Th, W2Tl, b2, nullptr, nullptr,
        sb, nullptr, nullptr, BROWS, D512, D512, 0);

    // launch 6: f_vit2 = LN(t) (+ split emit)
    ln_kernel<<<BROWS, 256>>>(sb, ln_g, ln_b, f_vit2, fvh, fvl);

    // launch 7: K7 f_global = BN(f_vit2 @ h1W + h1b); split(relu)
    hgemm<<<dim3(4, BROWS / 128), 256, SMEM_G>>>(
        nullptr, fvh, fvl, h1Th, h1Tl, h1b, bn1_g, bn1_b,
        f_global, hrh, hrl, BROWS, D512, D512, 2);

    // launch 8: K8 h2 = relu(BN(hr @ h2W + h2b))
    hgemm<<<dim3(2, BROWS / 128), 256, SMEM_G>>>(
        nullptr, hrh, hrl, h2Th, h2Tl, h2b, bn2_g, bn2_b,
        sc, nullptr, nullptr, BROWS, 256, D512, 3);

    // launch 9: pred
    pred_kernel<<<(BROWS * 40 + 127) / 128, 128>>>(sc, h3W, h3b, pred);

    (void)in_sizes; (void)n_in; (void)out_size;
}

// round 6
// speedup vs baseline: 2.4156x; 1.0064x over previous
#include <cuda_runtime.h>
#include <cuda_bf16.h>
#include <cstdint>
#include <math.h>

// ===========================================================================
// GMViT_mini — HMMA (mma.sync bf16) pipeline, 3-term bf16-split.
// R6: lnpool smem-staged max (no atomics); wconv split so K2 hgemm is the
//     ncu-profiled launch (overall #6).
// ===========================================================================

#define D512 512
#define NVIEWS 20
#define BROWS 4096
#define MROWS (BROWS * NVIEWS)   // 81920

#define OFF_FCNN    0LL
#define OFF_FVIT1   41943040LL
#define OFF_ATT     83886080LL
#define OFF_FVIT2   83968000LL
#define OFF_FGLOB   86065152LL
#define OFF_PRED    88162304LL

typedef unsigned short u16;

// -------------------- scratch (device globals, no allocs) ------------------
__device__ u16   g_fch[(size_t)MROWS * D512];
__device__ u16   g_fcl[(size_t)MROWS * D512];
__device__ float g_x1 [(size_t)MROWS * D512];
__device__ u16   g_sah[(size_t)BROWS * D512];
__device__ u16   g_sal[(size_t)BROWS * D512];
__device__ float g_sb [(size_t)BROWS * D512];
__device__ u16   g_fvh[(size_t)BROWS * D512];
__device__ u16   g_fvl[(size_t)BROWS * D512];
__device__ u16   g_hrh[(size_t)BROWS * D512];
__device__ u16   g_hrl[(size_t)BROWS * D512];
__device__ float g_sc [(size_t)BROWS * 256];
__device__ u16 g_WeTh[512 * 512], g_WeTl[512 * 512];
__device__ u16 g_W1Th[512 * 512], g_W1Tl[512 * 512];
__device__ u16 g_W2Th[512 * 512], g_W2Tl[512 * 512];
__device__ u16 g_h1Th[512 * 512], g_h1Tl[512 * 512];
__device__ u16 g_h2Th[256 * 512], g_h2Tl[256 * 512];

// ============================ helpers ======================================
__device__ __forceinline__ uint32_t smem_u32(const void* p) {
    uint32_t a;
    asm("{ .reg .u64 t; cvta.to.shared.u64 t, %1; cvt.u32.u64 %0, t; }"
        : "=r"(a) : "l"(p));
    return a;
}
#define CP16(d, s) \
    asm volatile("cp.async.cg.shared.global [%0], [%1], 16;" :: "r"(d), "l"(s))
#define CP_COMMIT() asm volatile("cp.async.commit_group;" ::)
#define CP_WAIT0()  asm volatile("cp.async.wait_group 0;" ::)

__device__ __forceinline__ void ldsm4(uint32_t& r0, uint32_t& r1, uint32_t& r2,
                                      uint32_t& r3, uint32_t addr) {
    asm volatile("ldmatrix.sync.aligned.m8n8.x4.shared.b16 {%0,%1,%2,%3}, [%4];"
                 : "=r"(r0), "=r"(r1), "=r"(r2), "=r"(r3) : "r"(addr));
}
__device__ __forceinline__ void mma16816(float* c, const uint32_t* a,
                                         const uint32_t* b) {
    asm volatile(
        "mma.sync.aligned.m16n8k16.row.col.f32.bf16.bf16.f32 "
        "{%0,%1,%2,%3}, {%4,%5,%6,%7}, {%8,%9}, {%0,%1,%2,%3};"
        : "+f"(c[0]), "+f"(c[1]), "+f"(c[2]), "+f"(c[3])
        : "r"(a[0]), "r"(a[1]), "r"(a[2]), "r"(a[3]), "r"(b[0]), "r"(b[1]));
}
__device__ __forceinline__ void split2(float a, float b, uint32_t& hi, uint32_t& lo) {
    __nv_bfloat16 ha = __float2bfloat16(a), hb = __float2bfloat16(b);
    float ra = a - __bfloat162float(ha), rb = b - __bfloat162float(hb);
    __nv_bfloat16 la = __float2bfloat16(ra), lb = __float2bfloat16(rb);
    hi = ((uint32_t)__bfloat16_as_ushort(hb) << 16) | (uint32_t)__bfloat16_as_ushort(ha);
    lo = ((uint32_t)__bfloat16_as_ushort(lb) << 16) | (uint32_t)__bfloat16_as_ushort(la);
}

// ============================ hgemm ========================================
// C[M,N] = (Ah+Al)[M,K] @ (Bh+Bl)[N,K]^T + bias   (3-term bf16 split)
// CTA 128x128, BK=32, 8 warps (64x32 each), cp.async double buffer.
// If Af != null, A is loaded fp32 and split in-kernel.
// epi 0: C=v
//     1: C=v;            C2h/C2l = split(v)
//     2: w=bn(v); C=w;   C2h/C2l = split(relu(w))
//     3: C=relu(bn(v))
#define TILE_B   10240
#define STAGE_B  (4 * TILE_B)
#define SMEM_G   (2 * STAGE_B)

__global__ __launch_bounds__(256, 2)
void hgemm(const float* __restrict__ Af,
           const u16* __restrict__ Ah, const u16* __restrict__ Al,
           const u16* __restrict__ Bh, const u16* __restrict__ Bl,
           const float* __restrict__ bias,
           const float* __restrict__ gamma, const float* __restrict__ beta,
           float* __restrict__ C, u16* __restrict__ C2h, u16* __restrict__ C2l,
           int M, int N, int K, int epi)
{
    extern __shared__ char sm[];
    const int tid  = threadIdx.x;
    const int lane = tid & 31;
    const int wid  = tid >> 5;
    const int wm   = wid >> 2;
    const int wn   = wid & 3;
    const int row0 = blockIdx.y * 128;
    const int col0 = blockIdx.x * 128;
    const bool useAf = (Af != nullptr);

    float acc[4][4][4];
#pragma unroll
    for (int i = 0; i < 4; i++)
#pragma unroll
        for (int j = 0; j < 4; j++)
#pragma unroll
            for (int q = 0; q < 4; q++) acc[i][j][q] = 0.0f;

    const int fr = tid >> 1;
    const int fc = (tid & 1) * 16;

    auto load_async = [&](int kb, int buf) {
        const int k0 = kb * 32;
        char* base = sm + buf * STAGE_B;
        if (!useAf) {
#pragma unroll
            for (int j = 0; j < 2; j++) {
                int ch = tid + j * 256;
                int r = ch >> 2, c = ch & 3;
                uint32_t d = smem_u32(base + r * 80 + c * 16);
                CP16(d, Ah + (size_t)(row0 + r) * K + k0 + c * 8);
                CP16(d + TILE_B, Al + (size_t)(row0 + r) * K + k0 + c * 8);
            }
        }
#pragma unroll
        for (int j = 0; j < 2; j++) {
            int ch = tid + j * 256;
            int r = ch >> 2, c = ch & 3;
            uint32_t d = smem_u32(base + 2 * TILE_B + r * 80 + c * 16);
            CP16(d, Bh + (size_t)(col0 + r) * K + k0 + c * 8);
            CP16(d + TILE_B, Bl + (size_t)(col0 + r) * K + k0 + c * 8);
        }
    };
    auto ldg_af = [&](int kb, float4* f) {
        const float* p = Af + (size_t)(row0 + fr) * K + kb * 32 + fc;
        f[0] = *(const float4*)p;       f[1] = *(const float4*)(p + 4);
        f[2] = *(const float4*)(p + 8); f[3] = *(const float4*)(p + 12);
    };
    auto sts_af = [&](int buf, const float4* f) {
        char* base = sm + buf * STAGE_B;
        uint4 uh0, uh1, ul0, ul1;
        split2(f[0].x, f[0].y, uh0.x, ul0.x);
        split2(f[0].z, f[0].w, uh0.y, ul0.y);
        split2(f[1].x, f[1].y, uh0.z, ul0.z);
        split2(f[1].z, f[1].w, uh0.w, ul0.w);
        split2(f[2].x, f[2].y, uh1.x, ul1.x);
        split2(f[2].z, f[2].w, uh1.y, ul1.y);
        split2(f[3].x, f[3].y, uh1.z, ul1.z);
        split2(f[3].z, f[3].w, uh1.w, ul1.w);
        char* p0 = base + fr * 80 + (fc >> 3) * 16;
        *(uint4*)(p0)               = uh0;
        *(uint4*)(p0 + 16)          = uh1;
        *(uint4*)(p0 + TILE_B)      = ul0;
        *(uint4*)(p0 + TILE_B + 16) = ul1;
    };

    float4 xf[4];
    if (useAf) { ldg_af(0, xf); sts_af(0, xf); }
    load_async(0, 0);
    CP_COMMIT();

    const int nkb = K / 32;
    for (int kb = 0; kb < nkb; kb++) {
        CP_WAIT0();
        __syncthreads();
        if (kb + 1 < nkb) {
            if (useAf) ldg_af(kb + 1, xf);
            load_async(kb + 1, (kb + 1) & 1);
            CP_COMMIT();
        }

        char* base = sm + (kb & 1) * STAGE_B;
        const uint32_t sA = smem_u32(base);
        const uint32_t sB = smem_u32(base + 2 * TILE_B);

#pragma unroll
        for (int ks = 0; ks < 2; ks++) {
            const int k0 = ks * 16;
            uint32_t bh[8], bl[8];
#pragma unroll
            for (int nt = 0; nt < 2; nt++) {
                int n = wn * 32 + nt * 16 + ((lane >> 4) << 3) + (lane & 7);
                int k = k0 + ((lane >> 3) & 1) * 8;
                uint32_t ad = sB + (uint32_t)(n * 80 + k * 2);
                ldsm4(bh[nt*4+0], bh[nt*4+1], bh[nt*4+2], bh[nt*4+3], ad);
                ldsm4(bl[nt*4+0], bl[nt*4+1], bl[nt*4+2], bl[nt*4+3], ad + TILE_B);
            }
#pragma unroll
            for (int mi = 0; mi < 4; mi++) {
                int m = wm * 64 + mi * 16 + (lane & 15);
                int k = k0 + (lane >> 4) * 8;
                uint32_t ad = sA + (uint32_t)(m * 80 + k * 2);
                uint32_t ah[4], al[4];
                ldsm4(ah[0], ah[1], ah[2], ah[3], ad);
                ldsm4(al[0], al[1], al[2], al[3], ad + TILE_B);
#pragma unroll
                for (int ni = 0; ni < 4; ni++) {
                    mma16816(acc[mi][ni], ah, &bh[ni * 2]);
                    mma16816(acc[mi][ni], ah, &bl[ni * 2]);
                    mma16816(acc[mi][ni], al, &bh[ni * 2]);
                }
            }
        }
        if (kb + 1 < nkb && useAf) sts_af((kb + 1) & 1, xf);
    }

    // epilogue
    const float inv = rsqrtf(1.0f + 1e-5f);
    const int rb = row0 + wm * 64 + (lane >> 2);
    const int cb = col0 + wn * 32 + (lane & 3) * 2;

#pragma unroll
    for (int mi = 0; mi < 4; mi++) {
#pragma unroll
        for (int ni = 0; ni < 4; ni++) {
            const int c = cb + ni * 8;
            float b0 = bias[c], b1 = bias[c + 1];
            float g0 = 0.f, g1 = 0.f, s0 = 0.f, s1 = 0.f;
            if (epi >= 2) { g0 = gamma[c] * inv; g1 = gamma[c+1] * inv;
                            s0 = beta[c];       s1 = beta[c+1]; }
#pragma unroll
            for (int h = 0; h < 2; h++) {
                const int r = rb + mi * 16 + h * 8;
                float v0 = acc[mi][ni][h * 2 + 0] + b0;
                float v1 = acc[mi][ni][h * 2 + 1] + b1;
                if (epi >= 2) { v0 = v0 * g0 + s0; v1 = v1 * g1 + s1; }
                if (epi == 3) { v0 = fmaxf(v0, 0.f); v1 = fmaxf(v1, 0.f); }
                *(float2*)(C + (size_t)r * N + c) = make_float2(v0, v1);
                if (epi == 1 || epi == 2) {
                    float w0 = (epi == 2) ? fmaxf(v0, 0.f) : v0;
                    float w1 = (epi == 2) ? fmaxf(v1, 0.f) : v1;
                    uint32_t hi, lo;
                    split2(w0, w1, hi, lo);
                    *(uint32_t*)(C2h + (size_t)r * N + c) = hi;
                    *(uint32_t*)(C2l + (size_t)r * N + c) = lo;
                }
            }
        }
    }
}

// ======= batched weight transpose + bf16 split: W[K,N] -> T[N,K] ===========
// Two variants to control launch count/position. K fixed at 512.
__device__ __forceinline__ void wconv_tile(const float* W, u16* Th, u16* Tl,
                                           int N, int n0, int k0, int tx, int ty,
                                           float t[32][33])
{
#pragma unroll
    for (int i = ty; i < 32; i += 8)
        t[i][tx] = W[(size_t)(k0 + i) * N + n0 + tx];
    __syncthreads();
#pragma unroll
    for (int i = ty; i < 32; i += 8) {
        float v = t[tx][i];
        __nv_bfloat16 h = __float2bfloat16(v);
        __nv_bfloat16 l = __float2bfloat16(v - __bfloat162float(h));
        size_t o = (size_t)(n0 + i) * 512 + k0 + tx;
        Th[o] = __bfloat16_as_ushort(h);
        Tl[o] = __bfloat16_as_ushort(l);
    }
}
__global__ __launch_bounds__(256)
void wconv_a(const float* __restrict__ We,  u16* WeTh, u16* WeTl,
             const float* __restrict__ W1,  u16* W1Th, u16* W1Tl,
             const float* __restrict__ W2,  u16* W2Th, u16* W2Tl)
{
    __shared__ float t[32][33];
    const float* W; u16* Th; u16* Tl;
    switch (blockIdx.z) {
        case 0: W = We; Th = WeTh; Tl = WeTl; break;
        case 1: W = W1; Th = W1Th; Tl = W1Tl; break;
        default:W = W2; Th = W2Th; Tl = W2Tl; break;
    }
    wconv_tile(W, Th, Tl, 512, blockIdx.x * 32, blockIdx.y * 32,
               threadIdx.x & 31, threadIdx.x >> 5, t);
}
__global__ __launch_bounds__(256)
void wconv_b(const float* __restrict__ h1W, u16* h1Th, u16* h1Tl,
             const float* __restrict__ h2W, u16* h2Th, u16* h2Tl)
{
    __shared__ float t[32][33];
    if (blockIdx.z == 0) {
        wconv_tile(h1W, h1Th, h1Tl, 512, blockIdx.x * 32, blockIdx.y * 32,
                   threadIdx.x & 31, threadIdx.x >> 5, t);
    } else {
        if (blockIdx.x >= 8) return;
        wconv_tile(h2W, h2Th, h2Tl, 256, blockIdx.x * 32, blockIdx.y * 32,
                   threadIdx.x & 31, threadIdx.x >> 5, t);
    }
}

// ============ fused: LN(x1)+att over 20 views, maxpool + split =============
// grid = BROWS, 640 threads (20 warps, warp w -> view-row w). Raw x staged in
// smem; 20-view max via LDS.64 (no atomics).
__global__ __launch_bounds__(640)
void lnpool_kernel(const float* __restrict__ X,
                   const float* __restrict__ g, const float* __restrict__ b,
                   const float* __restrict__ Wa, const float* __restrict__ ba,
                   float* __restrict__ Y, float* __restrict__ att,
                   u16* __restrict__ Ph, u16* __restrict__ Pl)
{
    __shared__ float sx[NVIEWS][D512];     // 40 KB
    const int obj  = blockIdx.x;
    const int tid  = threadIdx.x;
    const int w    = tid >> 5;
    const int lane = tid & 31;

    const int row = obj * NVIEWS + w;
    const float* xr = X + (size_t)row * D512;

    float xv[16];
    float s = 0.f, ss = 0.f;
#pragma unroll
    for (int i = 0; i < 16; i++) {
        float v = xr[lane + i * 32];
        xv[i] = v; s += v; ss += v * v;
        sx[w][lane + i * 32] = v;
    }
#pragma unroll
    for (int o = 16; o > 0; o >>= 1) {
        s  += __shfl_xor_sync(0xffffffffu, s,  o);
        ss += __shfl_xor_sync(0xffffffffu, ss, o);
    }
    const float mean = s * (1.0f / 512.0f);
    const float var  = ss * (1.0f / 512.0f) - mean * mean;
    const float rstd = rsqrtf(var + 1e-5f);

    float* yr = Y + (size_t)row * D512;
    float d = 0.f;
#pragma unroll
    for (int i = 0; i < 16; i++) {
        int c = lane + i * 32;
        float y = (xv[i] - mean) * rstd * __ldg(g + c) + __ldg(b + c);
        yr[c] = y;
        d += y * __ldg(Wa + c);
    }
#pragma unroll
    for (int o = 16; o > 0; o >>= 1)
        d += __shfl_xor_sync(0xffffffffu, d, o);
    if (lane == 0)
        att[row] = 1.0f / (1.0f + expf(-(d + ba[0])));

    __syncthreads();
    if (tid < 256) {
        const int c = tid * 2;
        float2 m = *(const float2*)&sx[0][c];
#pragma unroll
        for (int v = 1; v < NVIEWS; v++) {
            float2 t = *(const float2*)&sx[v][c];
            m.x = fmaxf(m.x, t.x); m.y = fmaxf(m.y, t.y);
        }
        uint32_t hi, lo;
        split2(m.x, m.y, hi, lo);
        *(uint32_t*)(Ph + (size_t)obj * D512 + c) = hi;
        *(uint32_t*)(Pl + (size_t)obj * D512 + c) = lo;
    }
}

// ============================ LayerNorm (+split) ===========================
__global__ __launch_bounds__(256)
void ln_kernel(const float* __restrict__ X,
               const float* __restrict__ g, const float* __restrict__ b,
               float* __restrict__ Y, u16* __restrict__ Yh, u16* __restrict__ Yl)
{
    const int row = blockIdx.x;
    const int tid = threadIdx.x;
    const float* xr = X + (size_t)row * D512;

    float x0 = xr[tid], x1 = xr[tid + 256];
    float s = x0 + x1, ss = x0 * x0 + x1 * x1;
#pragma unroll
    for (int o = 16; o > 0; o >>= 1) {
        s  += __shfl_xor_sync(0xffffffffu, s,  o);
        ss += __shfl_xor_sync(0xffffffffu, ss, o);
    }
    __shared__ float rs[8], rss[8];
    const int w = tid >> 5, lane = tid & 31;
    if (lane == 0) { rs[w] = s; rss[w] = ss; }
    __syncthreads();
    float tots = 0.f, totss = 0.f;
#pragma unroll
    for (int i = 0; i < 8; i++) { tots += rs[i]; totss += rss[i]; }
    const float mean = tots * (1.0f / 512.0f);
    const float var  = totss * (1.0f / 512.0f) - mean * mean;
    const float rstd = rsqrtf(var + 1e-5f);
    float y0 = (x0 - mean) * rstd * g[tid]       + b[tid];
    float y1 = (x1 - mean) * rstd * g[tid + 256] + b[tid + 256];
    float* yr = Y + (size_t)row * D512;
    yr[tid] = y0; yr[tid + 256] = y1;

    __nv_bfloat16 h0 = __float2bfloat16(y0);
    __nv_bfloat16 h1 = __float2bfloat16(y1);
    Yh[(size_t)row * D512 + tid]       = __bfloat16_as_ushort(h0);
    Yh[(size_t)row * D512 + tid + 256] = __bfloat16_as_ushort(h1);
    Yl[(size_t)row * D512 + tid]       =
        __bfloat16_as_ushort(__float2bfloat16(y0 - __bfloat162float(h0)));
    Yl[(size_t)row * D512 + tid + 256] =
        __bfloat16_as_ushort(__float2bfloat16(y1 - __bfloat162float(h1)));
}

// ============================ pred =========================================
__global__ void pred_kernel(const float* __restrict__ Hm, const float* __restrict__ W,
                            const float* __restrict__ bias, float* __restrict__ P)
{
    int i = blockIdx.x * blockDim.x + threadIdx.x;
    if (i >= BROWS * 40) return;
    int r = i / 40, n = i % 40;
    const float* h = Hm + (size_t)r * 256;
    float acc = bias[n];
#pragma unroll 8
    for (int k = 0; k < 256; k++)
        acc = fmaf(h[k], W[k * 40 + n], acc);
    P[i] = acc;
}

// ===========================================================================
extern "C" void kernel_launch(void* const* d_in, const int* in_sizes, int n_in,
                              void* d_out, int out_size)
{
    const float* x     = (const float*)d_in[0];
    const float* We    = (const float*)d_in[1];
    const float* be    = (const float*)d_in[2];
    const float* W1    = (const float*)d_in[3];
    const float* b1    = (const float*)d_in[4];
    const float* Wa    = (const float*)d_in[5];
    const float* ba    = (const float*)d_in[6];
    const float* W2    = (const float*)d_in[7];
    const float* b2    = (const float*)d_in[8];
    const float* ln_g  = (const float*)d_in[9];
    const float* ln_b  = (const float*)d_in[10];
    const float* h1W   = (const float*)d_in[11];
    const float* h1b   = (const float*)d_in[12];
    const float* bn1_g = (const float*)d_in[13];
    const float* bn1_b = (const float*)d_in[14];
    const float* h2W   = (const float*)d_in[15];
    const float* h2b   = (const float*)d_in[16];
    const float* bn2_g = (const float*)d_in[17];
    const float* bn2_b = (const float*)d_in[18];
    const float* h3W   = (const float*)d_in[19];
    const float* h3b   = (const float*)d_in[20];

    float* out      = (float*)d_out;
    float* f_cnn    = out + OFF_FCNN;
    float* f_vit1   = out + OFF_FVIT1;
    float* att      = out + OFF_ATT;
    float* f_vit2   = out + OFF_FVIT2;
    float* f_global = out + OFF_FGLOB;
    float* pred     = out + OFF_PRED;

    u16 *fch,*fcl,*sah,*sal,*fvh,*fvl,*hrh,*hrl;
    u16 *WeTh,*WeTl,*W1Th,*W1Tl,*W2Th,*W2Tl,*h1Th,*h1Tl,*h2Th,*h2Tl;
    float *x1s,*sb,*sc;
    { void* p; cudaGetSymbolAddress(&p, g_fch); fch = (u16*)p; }
    { void* p; cudaGetSymbolAddress(&p, g_fcl); fcl = (u16*)p; }
    { void* p; cudaGetSymbolAddress(&p, g_x1);  x1s = (float*)p; }
    { void* p; cudaGetSymbolAddress(&p, g_sah); sah = (u16*)p; }
    { void* p; cudaGetSymbolAddress(&p, g_sal); sal = (u16*)p; }
    { void* p; cudaGetSymbolAddress(&p, g_sb);  sb  = (float*)p; }
    { void* p; cudaGetSymbolAddress(&p, g_fvh); fvh = (u16*)p; }
    { void* p; cudaGetSymbolAddress(&p, g_fvl); fvl = (u16*)p; }
    { void* p; cudaGetSymbolAddress(&p, g_hrh); hrh = (u16*)p; }
    { void* p; cudaGetSymbolAddress(&p, g_hrl); hrl = (u16*)p; }
    { void* p; cudaGetSymbolAddress(&p, g_sc);  sc  = (float*)p; }
    { void* p; cudaGetSymbolAddress(&p, g_WeTh); WeTh = (u16*)p; }
    { void* p; cudaGetSymbolAddress(&p, g_WeTl); WeTl = (u16*)p; }
    { void* p; cudaGetSymbolAddress(&p, g_W1Th); W1Th = (u16*)p; }
    { void* p; cudaGetSymbolAddress(&p, g_W1Tl); W1Tl = (u16*)p; }
    { void* p; cudaGetSymbolAddress(&p, g_W2Th); W2Th = (u16*)p; }
    { void* p; cudaGetSymbolAddress(&p, g_W2Tl); W2Tl = (u16*)p; }
    { void* p; cudaGetSymbolAddress(&p, g_h1Th); h1Th = (u16*)p; }
    { void* p; cudaGetSymbolAddress(&p, g_h1Tl); h1Tl = (u16*)p; }
    { void* p; cudaGetSymbolAddress(&p, g_h2Th); h2Th = (u16*)p; }
    { void* p; cudaGetSymbolAddress(&p, g_h2Tl); h2Tl = (u16*)p; }

    cudaFuncSetAttribute(hgemm, cudaFuncAttributeMaxDynamicSharedMemorySize, SMEM_G);

    // launch 1+2: weight transposes+splits (split so K2 lands at overall #6)
    wconv_a<<<dim3(16, 16, 3), 256>>>(We, WeTh, WeTl, W1, W1Th, W1Tl,
                                      W2, W2Th, W2Tl);
    wconv_b<<<dim3(16, 16, 2), 256>>>(h1W, h1Th, h1Tl, h2W, h2Th, h2Tl);

    // launch 3: K1 f_cnn = x @ We + be  (fp32 A, split emit)
    hgemm<<<dim3(4, MROWS / 128), 256, SMEM_G>>>(
        x, nullptr, nullptr, WeTh, WeTl, be, nullptr, nullptr,
        f_cnn, fch, fcl, MROWS, D512, D512, 1);

    // launch 4 (ncu target, overall #6): K2 x1 = f_cnn @ W1 + b1
    hgemm<<<dim3(4, MROWS / 128), 256, SMEM_G>>>(
        nullptr, fch, fcl, W1Th, W1Tl, b1, nullptr, nullptr,
        x1s, nullptr, nullptr, MROWS, D512, D512, 0);

    // launch 5: fused LN + att + maxpool + split
    lnpool_kernel<<<BROWS, 640>>>(x1s, ln_g, ln_b, Wa, ba,
                                  f_vit1, att, sah, sal);

    // launch 6: K5 t = pre @ W2 + b2
    hgemm<<<dim3(4, BROWS / 128), 256, SMEM_G>>>(
        nullptr, sah, sal, W2Th, W2Tl, b2, nullptr, nullptr,
        sb, nullptr, nullptr, BROWS, D512, D512, 0);

    // launch 7: f_vit2 = LN(t) (+ split emit)
    ln_kernel<<<BROWS, 256>>>(sb, ln_g, ln_b, f_vit2, fvh, fvl);

    // launch 8: K7 f_global = BN(f_vit2 @ h1W + h1b); split(relu)
    hgemm<<<dim3(4, BROWS / 128), 256, SMEM_G>>>(
        nullptr, fvh, fvl, h1Th, h1Tl, h1b, bn1_g, bn1_b,
        f_global, hrh, hrl, BROWS, D512, D512, 2);

    // launch 9: K8 h2 = relu(BN(hr @ h2W + h2b))
    hgemm<<<dim3(2, BROWS / 128), 256, SMEM_G>>>(
        nullptr, hrh, hrl, h2Th, h2Tl, h2b, bn2_g, bn2_b,
        sc, nullptr, nullptr, BROWS, 256, D512, 3);

    // launch 10: pred
    pred_kernel<<<(BROWS * 40 + 127) / 128, 128>>>(sc, h3W, h3b, pred);

    (void)in_sizes; (void)n_in; (void)out_size;
}

// round 9
// speedup vs baseline: 2.4198x; 1.0017x over previous
#include <cuda_runtime.h>
#include <cuda_bf16.h>
#include <cstdint>
#include <math.h>

// ===========================================================================
// GMViT_mini — HMMA (mma.sync bf16) pipeline, 3-term bf16-split.
// R8 == R7 resubmit (container infra failure, kernel never ran):
// hgemm inner loop restructured — batched ldsm (MLP=12), pass-major mma
// order (16-issue RAW distance). Everything else frozen vs R6.
// ===========================================================================

#define D512 512
#define NVIEWS 20
#define BROWS 4096
#define MROWS (BROWS * NVIEWS)   // 81920

#define OFF_FCNN    0LL
#define OFF_FVIT1   41943040LL
#define OFF_ATT     83886080LL
#define OFF_FVIT2   83968000LL
#define OFF_FGLOB   86065152LL
#define OFF_PRED    88162304LL

typedef unsigned short u16;

// -------------------- scratch (device globals, no allocs) ------------------
__device__ u16   g_fch[(size_t)MROWS * D512];
__device__ u16   g_fcl[(size_t)MROWS * D512];
__device__ float g_x1 [(size_t)MROWS * D512];
__device__ u16   g_sah[(size_t)BROWS * D512];
__device__ u16   g_sal[(size_t)BROWS * D512];
__device__ float g_sb [(size_t)BROWS * D512];
__device__ u16   g_fvh[(size_t)BROWS * D512];
__device__ u16   g_fvl[(size_t)BROWS * D512];
__device__ u16   g_hrh[(size_t)BROWS * D512];
__device__ u16   g_hrl[(size_t)BROWS * D512];
__device__ float g_sc [(size_t)BROWS * 256];
__device__ u16 g_WeTh[512 * 512], g_WeTl[512 * 512];
__device__ u16 g_W1Th[512 * 512], g_W1Tl[512 * 512];
__device__ u16 g_W2Th[512 * 512], g_W2Tl[512 * 512];
__device__ u16 g_h1Th[512 * 512], g_h1Tl[512 * 512];
__device__ u16 g_h2Th[256 * 512], g_h2Tl[256 * 512];

// ============================ helpers ======================================
__device__ __forceinline__ uint32_t smem_u32(const void* p) {
    uint32_t a;
    asm("{ .reg .u64 t; cvta.to.shared.u64 t, %1; cvt.u32.u64 %0, t; }"
        : "=r"(a) : "l"(p));
    return a;
}
#define CP16(d, s) \
    asm volatile("cp.async.cg.shared.global [%0], [%1], 16;" :: "r"(d), "l"(s))
#define CP_COMMIT() asm volatile("cp.async.commit_group;" ::)
#define CP_WAIT0()  asm volatile("cp.async.wait_group 0;" ::)

__device__ __forceinline__ void ldsm4(uint32_t& r0, uint32_t& r1, uint32_t& r2,
                                      uint32_t& r3, uint32_t addr) {
    asm volatile("ldmatrix.sync.aligned.m8n8.x4.shared.b16 {%0,%1,%2,%3}, [%4];"
                 : "=r"(r0), "=r"(r1), "=r"(r2), "=r"(r3) : "r"(addr));
}
__device__ __forceinline__ void mma16816(float* c, const uint32_t* a,
                                         const uint32_t* b) {
    asm volatile(
        "mma.sync.aligned.m16n8k16.row.col.f32.bf16.bf16.f32 "
        "{%0,%1,%2,%3}, {%4,%5,%6,%7}, {%8,%9}, {%0,%1,%2,%3};"
        : "+f"(c[0]), "+f"(c[1]), "+f"(c[2]), "+f"(c[3])
        : "r"(a[0]), "r"(a[1]), "r"(a[2]), "r"(a[3]), "r"(b[0]), "r"(b[1]));
}
__device__ __forceinline__ void split2(float a, float b, uint32_t& hi, uint32_t& lo) {
    __nv_bfloat16 ha = __float2bfloat16(a), hb = __float2bfloat16(b);
    float ra = a - __bfloat162float(ha), rb = b - __bfloat162float(hb);
    __nv_bfloat16 la = __float2bfloat16(ra), lb = __float2bfloat16(rb);
    hi = ((uint32_t)__bfloat16_as_ushort(hb) << 16) | (uint32_t)__bfloat16_as_ushort(ha);
    lo = ((uint32_t)__bfloat16_as_ushort(lb) << 16) | (uint32_t)__bfloat16_as_ushort(la);
}

// ============================ hgemm ========================================
#define TILE_B   10240
#define STAGE_B  (4 * TILE_B)
#define SMEM_G   (2 * STAGE_B)

__global__ __launch_bounds__(256, 2)
void hgemm(const float* __restrict__ Af,
           const u16* __restrict__ Ah, const u16* __restrict__ Al,
           const u16* __restrict__ Bh, const u16* __restrict__ Bl,
           const float* __restrict__ bias,
           const float* __restrict__ gamma, const float* __restrict__ beta,
           float* __restrict__ C, u16* __restrict__ C2h, u16* __restrict__ C2l,
           int M, int N, int K, int epi)
{
    extern __shared__ char sm[];
    const int tid  = threadIdx.x;
    const int lane = tid & 31;
    const int wid  = tid >> 5;
    const int wm   = wid >> 2;
    const int wn   = wid & 3;
    const int row0 = blockIdx.y * 128;
    const int col0 = blockIdx.x * 128;
    const bool useAf = (Af != nullptr);

    float acc[4][4][4];
#pragma unroll
    for (int i = 0; i < 4; i++)
#pragma unroll
        for (int j = 0; j < 4; j++)
#pragma unroll
            for (int q = 0; q < 4; q++) acc[i][j][q] = 0.0f;

    const int fr = tid >> 1;
    const int fc = (tid & 1) * 16;

    auto load_async = [&](int kb, int buf) {
        const int k0 = kb * 32;
        char* base = sm + buf * STAGE_B;
        if (!useAf) {
#pragma unroll
            for (int j = 0; j < 2; j++) {
                int ch = tid + j * 256;
                int r = ch >> 2, c = ch & 3;
                uint32_t d = smem_u32(base + r * 80 + c * 16);
                CP16(d, Ah + (size_t)(row0 + r) * K + k0 + c * 8);
                CP16(d + TILE_B, Al + (size_t)(row0 + r) * K + k0 + c * 8);
            }
        }
#pragma unroll
        for (int j = 0; j < 2; j++) {
            int ch = tid + j * 256;
            int r = ch >> 2, c = ch & 3;
            uint32_t d = smem_u32(base + 2 * TILE_B + r * 80 + c * 16);
            CP16(d, Bh + (size_t)(col0 + r) * K + k0 + c * 8);
            CP16(d + TILE_B, Bl + (size_t)(col0 + r) * K + k0 + c * 8);
        }
    };
    auto ldg_af = [&](int kb, float4* f) {
        const float* p = Af + (size_t)(row0 + fr) * K + kb * 32 + fc;
        f[0] = *(const float4*)p;       f[1] = *(const float4*)(p + 4);
        f[2] = *(const float4*)(p + 8); f[3] = *(const float4*)(p + 12);
    };
    auto sts_af = [&](int buf, const float4* f) {
        char* base = sm + buf * STAGE_B;
        uint4 uh0, uh1, ul0, ul1;
        split2(f[0].x, f[0].y, uh0.x, ul0.x);
        split2(f[0].z, f[0].w, uh0.y, ul0.y);
        split2(f[1].x, f[1].y, uh0.z, ul0.z);
        split2(f[1].z, f[1].w, uh0.w, ul0.w);
        split2(f[2].x, f[2].y, uh1.x, ul1.x);
        split2(f[2].z, f[2].w, uh1.y, ul1.y);
        split2(f[3].x, f[3].y, uh1.z, ul1.z);
        split2(f[3].z, f[3].w, uh1.w, ul1.w);
        char* p0 = base + fr * 80 + (fc >> 3) * 16;
        *(uint4*)(p0)               = uh0;
        *(uint4*)(p0 + 16)          = uh1;
        *(uint4*)(p0 + TILE_B)      = ul0;
        *(uint4*)(p0 + TILE_B + 16) = ul1;
    };

    float4 xf[4];
    if (useAf) { ldg_af(0, xf); sts_af(0, xf); }
    load_async(0, 0);
    CP_COMMIT();

    const int nkb = K / 32;
    for (int kb = 0; kb < nkb; kb++) {
        CP_WAIT0();
        __syncthreads();
        if (kb + 1 < nkb) {
            if (useAf) ldg_af(kb + 1, xf);
            load_async(kb + 1, (kb + 1) & 1);
            CP_COMMIT();
        }

        char* base = sm + (kb & 1) * STAGE_B;
        const uint32_t sA = smem_u32(base);
        const uint32_t sB = smem_u32(base + 2 * TILE_B);

#pragma unroll
        for (int ks = 0; ks < 2; ks++) {
            const int k0 = ks * 16;
            // ---- batched fragment loads: 12 ldsm issued back-to-back ----
            uint32_t bh[8], bl[8], ah[4][4], al[4][4];
#pragma unroll
            for (int nt = 0; nt < 2; nt++) {
                int n = wn * 32 + nt * 16 + ((lane >> 4) << 3) + (lane & 7);
                int k = k0 + ((lane >> 3) & 1) * 8;
                uint32_t ad = sB + (uint32_t)(n * 80 + k * 2);
                ldsm4(bh[nt*4+0], bh[nt*4+1], bh[nt*4+2], bh[nt*4+3], ad);
                ldsm4(bl[nt*4+0], bl[nt*4+1], bl[nt*4+2], bl[nt*4+3], ad + TILE_B);
            }
#pragma unroll
            for (int mi = 0; mi < 4; mi++) {
                int m = wm * 64 + mi * 16 + (lane & 15);
                int k = k0 + (lane >> 4) * 8;
                uint32_t ad = sA + (uint32_t)(m * 80 + k * 2);
                ldsm4(ah[mi][0], ah[mi][1], ah[mi][2], ah[mi][3], ad);
                ldsm4(al[mi][0], al[mi][1], al[mi][2], al[mi][3], ad + TILE_B);
            }
            // ---- pass-major mma: dependent mmas 16 issues apart ----
#pragma unroll
            for (int mi = 0; mi < 4; mi++)
#pragma unroll
                for (int ni = 0; ni < 4; ni++)
                    mma16816(acc[mi][ni], ah[mi], &bh[ni * 2]);
#pragma unroll
            for (int mi = 0; mi < 4; mi++)
#pragma unroll
                for (int ni = 0; ni < 4; ni++)
                    mma16816(acc[mi][ni], ah[mi], &bl[ni * 2]);
#pragma unroll
            for (int mi = 0; mi < 4; mi++)
#pragma unroll
                for (int ni = 0; ni < 4; ni++)
                    mma16816(acc[mi][ni], al[mi], &bh[ni * 2]);
        }
        if (kb + 1 < nkb && useAf) sts_af((kb + 1) & 1, xf);
    }

    // epilogue
    const float inv = rsqrtf(1.0f + 1e-5f);
    const int rb = row0 + wm * 64 + (lane >> 2);
    const int cb = col0 + wn * 32 + (lane & 3) * 2;

#pragma unroll
    for (int mi = 0; mi < 4; mi++) {
#pragma unroll
        for (int ni = 0; ni < 4; ni++) {
            const int c = cb + ni * 8;
            float b0 = bias[c], b1 = bias[c + 1];
            float g0 = 0.f, g1 = 0.f, s0 = 0.f, s1 = 0.f;
            if (epi >= 2) { g0 = gamma[c] * inv; g1 = gamma[c+1] * inv;
                            s0 = beta[c];       s1 = beta[c+1]; }
#pragma unroll
            for (int h = 0; h < 2; h++) {
                const int r = rb + mi * 16 + h * 8;
                float v0 = acc[mi][ni][h * 2 + 0] + b0;
                float v1 = acc[mi][ni][h * 2 + 1] + b1;
                if (epi >= 2) { v0 = v0 * g0 + s0; v1 = v1 * g1 + s1; }
                if (epi == 3) { v0 = fmaxf(v0, 0.f); v1 = fmaxf(v1, 0.f); }
                *(float2*)(C + (size_t)r * N + c) = make_float2(v0, v1);
                if (epi == 1 || epi == 2) {
                    float w0 = (epi == 2) ? fmaxf(v0, 0.f) : v0;
                    float w1 = (epi == 2) ? fmaxf(v1, 0.f) : v1;
                    uint32_t hi, lo;
                    split2(w0, w1, hi, lo);
                    *(uint32_t*)(C2h + (size_t)r * N + c) = hi;
                    *(uint32_t*)(C2l + (size_t)r * N + c) = lo;
                }
            }
        }
    }
}

// ======= batched weight transpose + bf16 split: W[K,N] -> T[N,K] ===========
__device__ __forceinline__ void wconv_tile(const float* W, u16* Th, u16* Tl,
                                           int N, int n0, int k0, int tx, int ty,
                                           float t[32][33])
{
#pragma unroll
    for (int i = ty; i < 32; i += 8)
        t[i][tx] = W[(size_t)(k0 + i) * N + n0 + tx];
    __syncthreads();
#pragma unroll
    for (int i = ty; i < 32; i += 8) {
        float v = t[tx][i];
        __nv_bfloat16 h = __float2bfloat16(v);
        __nv_bfloat16 l = __float2bfloat16(v - __bfloat162float(h));
        size_t o = (size_t)(n0 + i) * 512 + k0 + tx;
        Th[o] = __bfloat16_as_ushort(h);
        Tl[o] = __bfloat16_as_ushort(l);
    }
}
__global__ __launch_bounds__(256)
void wconv_a(const float* __restrict__ We,  u16* WeTh, u16* WeTl,
             const float* __restrict__ W1,  u16* W1Th, u16* W1Tl,
             const float* __restrict__ W2,  u16* W2Th, u16* W2Tl)
{
    __shared__ float t[32][33];
    const float* W; u16* Th; u16* Tl;
    switch (blockIdx.z) {
        case 0: W = We; Th = WeTh; Tl = WeTl; break;
        case 1: W = W1; Th = W1Th; Tl = W1Tl; break;
        default:W = W2; Th = W2Th; Tl = W2Tl; break;
    }
    wconv_tile(W, Th, Tl, 512, blockIdx.x * 32, blockIdx.y * 32,
               threadIdx.x & 31, threadIdx.x >> 5, t);
}
__global__ __launch_bounds__(256)
void wconv_b(const float* __restrict__ h1W, u16* h1Th, u16* h1Tl,
             const float* __restrict__ h2W, u16* h2Th, u16* h2Tl)
{
    __shared__ float t[32][33];
    if (blockIdx.z == 0) {
        wconv_tile(h1W, h1Th, h1Tl, 512, blockIdx.x * 32, blockIdx.y * 32,
                   threadIdx.x & 31, threadIdx.x >> 5, t);
    } else {
        if (blockIdx.x >= 8) return;
        wconv_tile(h2W, h2Th, h2Tl, 256, blockIdx.x * 32, blockIdx.y * 32,
                   threadIdx.x & 31, threadIdx.x >> 5, t);
    }
}

// ============ fused: LN(x1)+att over 20 views, maxpool + split =============
__global__ __launch_bounds__(640)
void lnpool_kernel(const float* __restrict__ X,
                   const float* __restrict__ g, const float* __restrict__ b,
                   const float* __restrict__ Wa, const float* __restrict__ ba,
                   float* __restrict__ Y, float* __restrict__ att,
                   u16* __restrict__ Ph, u16* __restrict__ Pl)
{
    __shared__ float sx[NVIEWS][D512];     // 40 KB
    const int obj  = blockIdx.x;
    const int tid  = threadIdx.x;
    const int w    = tid >> 5;
    const int lane = tid & 31;

    const int row = obj * NVIEWS + w;
    const float* xr = X + (size_t)row * D512;

    float xv[16];
    float s = 0.f, ss = 0.f;
#pragma unroll
    for (int i = 0; i < 16; i++) {
        float v = xr[lane + i * 32];
        xv[i] = v; s += v; ss += v * v;
        sx[w][lane + i * 32] = v;
    }
#pragma unroll
    for (int o = 16; o > 0; o >>= 1) {
        s  += __shfl_xor_sync(0xffffffffu, s,  o);
        ss += __shfl_xor_sync(0xffffffffu, ss, o);
    }
    const float mean = s * (1.0f / 512.0f);
    const float var  = ss * (1.0f / 512.0f) - mean * mean;
    const float rstd = rsqrtf(var + 1e-5f);

    float* yr = Y + (size_t)row * D512;
    float d = 0.f;
#pragma unroll
    for (int i = 0; i < 16; i++) {
        int c = lane + i * 32;
        float y = (xv[i] - mean) * rstd * __ldg(g + c) + __ldg(b + c);
        yr[c] = y;
        d += y * __ldg(Wa + c);
    }
#pragma unroll
    for (int o = 16; o > 0; o >>= 1)
        d += __shfl_xor_sync(0xffffffffu, d, o);
    if (lane == 0)
        att[row] = 1.0f / (1.0f + expf(-(d + ba[0])));

    __syncthreads();
    if (tid < 256) {
        const int c = tid * 2;
        float2 m = *(const float2*)&sx[0][c];
#pragma unroll
        for (int v = 1; v < NVIEWS; v++) {
            float2 t = *(const float2*)&sx[v][c];
            m.x = fmaxf(m.x, t.x); m.y = fmaxf(m.y, t.y);
        }
        uint32_t hi, lo;
        split2(m.x, m.y, hi, lo);
        *(uint32_t*)(Ph + (size_t)obj * D512 + c) = hi;
        *(uint32_t*)(Pl + (size_t)obj * D512 + c) = lo;
    }
}

// ============================ LayerNorm (+split) ===========================
__global__ __launch_bounds__(256)
void ln_kernel(const float* __restrict__ X,
               const float* __restrict__ g, const float* __restrict__ b,
               float* __restrict__ Y, u16* __restrict__ Yh, u16* __restrict__ Yl)
{
    const int row = blockIdx.x;
    const int tid = threadIdx.x;
    const float* xr = X + (size_t)row * D512;

    float x0 = xr[tid], x1 = xr[tid + 256];
    float s = x0 + x1, ss = x0 * x0 + x1 * x1;
#pragma unroll
    for (int o = 16; o > 0; o >>= 1) {
        s  += __shfl_xor_sync(0xffffffffu, s,  o);
        ss += __shfl_xor_sync(0xffffffffu, ss, o);
    }
    __shared__ float rs[8], rss[8];
    const int w = tid >> 5, lane = tid & 31;
    if (lane == 0) { rs[w] = s; rss[w] = ss; }
    __syncthreads();
    float tots = 0.f, totss = 0.f;
#pragma unroll
    for (int i = 0; i < 8; i++) { tots += rs[i]; totss += rss[i]; }
    const float mean = tots * (1.0f / 512.0f);
    const float var  = totss * (1.0f / 512.0f) - mean * mean;
    const float rstd = rsqrtf(var + 1e-5f);
    float y0 = (x0 - mean) * rstd * g[tid]       + b[tid];
    float y1 = (x1 - mean) * rstd * g[tid + 256] + b[tid + 256];
    float* yr = Y + (size_t)row * D512;
    yr[tid] = y0; yr[tid + 256] = y1;

    __nv_bfloat16 h0 = __float2bfloat16(y0);
    __nv_bfloat16 h1 = __float2bfloat16(y1);
    Yh[(size_t)row * D512 + tid]       = __bfloat16_as_ushort(h0);
    Yh[(size_t)row * D512 + tid + 256] = __bfloat16_as_ushort(h1);
    Yl[(size_t)row * D512 + tid]       =
        __bfloat16_as_ushort(__float2bfloat16(y0 - __bfloat162float(h0)));
    Yl[(size_t)row * D512 + tid + 256] =
        __bfloat16_as_ushort(__float2bfloat16(y1 - __bfloat162float(h1)));
}

// ============================ pred =========================================
__global__ void pred_kernel(const float* __restrict__ Hm, const float* __restrict__ W,
                            const float* __restrict__ bias, float* __restrict__ P)
{
    int i = blockIdx.x * blockDim.x + threadIdx.x;
    if (i >= BROWS * 40) return;
    int r = i / 40, n = i % 40;
    const float* h = Hm + (size_t)r * 256;
    float acc = bias[n];
#pragma unroll 8
    for (int k = 0; k < 256; k++)
        acc = fmaf(h[k], W[k * 40 + n], acc);
    P[i] = acc;
}

// ===========================================================================
extern "C" void kernel_launch(void* const* d_in, const int* in_sizes, int n_in,
                              void* d_out, int out_size)
{
    const float* x     = (const float*)d_in[0];
    const float* We    = (const float*)d_in[1];
    const float* be    = (const float*)d_in[2];
    const float* W1    = (const float*)d_in[3];
    const float* b1    = (const float*)d_in[4];
    const float* Wa    = (const float*)d_in[5];
    const float* ba    = (const float*)d_in[6];
    const float* W2    = (const float*)d_in[7];
    const float* b2    = (const float*)d_in[8];
    const float* ln_g  = (const float*)d_in[9];
    const float* ln_b  = (const float*)d_in[10];
    const float* h1W   = (const float*)d_in[11];
    const float* h1b   = (const float*)d_in[12];
    const float* bn1_g = (const float*)d_in[13];
    const float* bn1_b = (const float*)d_in[14];
    const float* h2W   = (const float*)d_in[15];
    const float* h2b   = (const float*)d_in[16];
    const float* bn2_g = (const float*)d_in[17];
    const float* bn2_b = (const float*)d_in[18];
    const float* h3W   = (const float*)d_in[19];
    const float* h3b   = (const float*)d_in[20];

    float* out      = (float*)d_out;
    float* f_cnn    = out + OFF_FCNN;
    float* f_vit1   = out + OFF_FVIT1;
    float* att      = out + OFF_ATT;
    float* f_vit2   = out + OFF_FVIT2;
    float* f_global = out + OFF_FGLOB;
    float* pred     = out + OFF_PRED;

    u16 *fch,*fcl,*sah,*sal,*fvh,*fvl,*hrh,*hrl;
    u16 *WeTh,*WeTl,*W1Th,*W1Tl,*W2Th,*W2Tl,*h1Th,*h1Tl,*h2Th,*h2Tl;
    float *x1s,*sb,*sc;
    { void* p; cudaGetSymbolAddress(&p, g_fch); fch = (u16*)p; }
    { void* p; cudaGetSymbolAddress(&p, g_fcl); fcl = (u16*)p; }
    { void* p; cudaGetSymbolAddress(&p, g_x1);  x1s = (float*)p; }
    { void* p; cudaGetSymbolAddress(&p, g_sah); sah = (u16*)p; }
    { void* p; cudaGetSymbolAddress(&p, g_sal); sal = (u16*)p; }
    { void* p; cudaGetSymbolAddress(&p, g_sb);  sb  = (float*)p; }
    { void* p; cudaGetSymbolAddress(&p, g_fvh); fvh = (u16*)p; }
    { void* p; cudaGetSymbolAddress(&p, g_fvl); fvl = (u16*)p; }
    { void* p; cudaGetSymbolAddress(&p, g_hrh); hrh = (u16*)p; }
    { void* p; cudaGetSymbolAddress(&p, g_hrl); hrl = (u16*)p; }
    { void* p; cudaGetSymbolAddress(&p, g_sc);  sc  = (float*)p; }
    { void* p; cudaGetSymbolAddress(&p, g_WeTh); WeTh = (u16*)p; }
    { void* p; cudaGetSymbolAddress(&p, g_WeTl); WeTl = (u16*)p; }
    { void* p; cudaGetSymbolAddress(&p, g_W1Th); W1Th = (u16*)p; }
    { void* p; cudaGetSymbolAddress(&p, g_W1Tl); W1Tl = (u16*)p; }
    { void* p; cudaGetSymbolAddress(&p, g_W2Th); W2Th = (u16*)p; }
    { void* p; cudaGetSymbolAddress(&p, g_W2Tl); W2Tl = (u16*)p; }
    { void* p; cudaGetSymbolAddress(&p, g_h1Th); h1Th = (u16*)p; }
    { void* p; cudaGetSymbolAddress(&p, g_h1Tl); h1Tl = (u16*)p; }
    { void* p; cudaGetSymbolAddress(&p, g_h2Th); h2Th = (u16*)p; }
    { void* p; cudaGetSymbolAddress(&p, g_h2Tl); h2Tl = (u16*)p; }

    cudaFuncSetAttribute(hgemm, cudaFuncAttributeMaxDynamicSharedMemorySize, SMEM_G);

    // launch 1+2: weight transposes+splits
    wconv_a<<<dim3(16, 16, 3), 256>>>(We, WeTh, WeTl, W1, W1Th, W1Tl,
                                      W2, W2Th, W2Tl);
    wconv_b<<<dim3(16, 16, 2), 256>>>(h1W, h1Th, h1Tl, h2W, h2Th, h2Tl);

    // launch 3: K1 f_cnn = x @ We + be  (fp32 A, split emit)
    hgemm<<<dim3(4, MROWS / 128), 256, SMEM_G>>>(
        x, nullptr, nullptr, WeTh, WeTl, be, nullptr, nullptr,
        f_cnn, fch, fcl, MROWS, D512, D512, 1);

    // launch 4 (ncu target, overall #6): K2 x1 = f_cnn @ W1 + b1
    hgemm<<<dim3(4, MROWS / 128), 256, SMEM_G>>>(
        nullptr, fch, fcl, W1Th, W1Tl, b1, nullptr, nullptr,
        x1s, nullptr, nullptr, MROWS, D512, D512, 0);

    // launch 5: fused LN + att + maxpool + split
    lnpool_kernel<<<BROWS, 640>>>(x1s, ln_g, ln_b, Wa, ba,
                                  f_vit1, att, sah, sal);

    // launch 6: K5 t = pre @ W2 + b2
    hgemm<<<dim3(4, BROWS / 128), 256, SMEM_G>>>(
        nullptr, sah, sal, W2Th, W2Tl, b2, nullptr, nullptr,
        sb, nullptr, nullptr, BROWS, D512, D512, 0);

    // launch 7: f_vit2 = LN(t) (+ split emit)
    ln_kernel<<<BROWS, 256>>>(sb, ln_g, ln_b, f_vit2, fvh, fvl);

    // launch 8: K7 f_global = BN(f_vit2 @ h1W + h1b); split(relu)
    hgemm<<<dim3(4, BROWS / 128), 256, SMEM_G>>>(
        nullptr, fvh, fvl, h1Th, h1Tl, h1b, bn1_g, bn1_b,
        f_global, hrh, hrl, BROWS, D512, D512, 2);

    // launch 9: K8 h2 = relu(BN(hr @ h2W + h2b))
    hgemm<<<dim3(2, BROWS / 128), 256, SMEM_G>>>(
        nullptr, hrh, hrl, h2Th, h2Tl, h2b, bn2_g, bn2_b,
        sc, nullptr, nullptr, BROWS, 256, D512, 3);

    // launch 10: pred
    pred_kernel<<<(BROWS * 40 + 127) / 128, 128>>>(sc, h3W, h3b, pred);

    (void)in_sizes; (void)n_in; (void)out_size;
}